// round 6
// baseline (speedup 1.0000x reference)
#include <cuda_runtime.h>
#include <cuda_bf16.h>
#include <math.h>
#include <stdint.h>

constexpr int cB = 1024, cS = 10, cN = 36, cF = 2048, cD = 2176;
constexpr int BSr = cB * cS, BNr = cB * cN, G3 = 3 * cF;
constexpr int K2D = 2 * cD, K2F = 2 * cF;        // 4352 / 4096
constexpr int KTD = cD / 64, KTF = cF / 64;      // 34 / 32 (base k-tiles)
constexpr int KT2D = 2 * KTD, KT2F = 2 * KTF;    // 68 / 64 (blocks per row-panel)

// fp32 scratch
__device__ float g_k[(size_t)BNr * cD];
__device__ float g_v[(size_t)BNr * cD];
__device__ float g_q[(size_t)BSr * cD];
__device__ float g_gi[(size_t)BSr * G3];
__device__ float g_gh[(size_t)BSr * G3];
__device__ float g_h[(size_t)BSr * cF];
__device__ float g_hnew[(size_t)BSr * cF];
__device__ float g_attn[(size_t)BSr * cN];
__device__ int g_mask_mode;

// bf16 [hi|lo] split operands, pre-swizzled 128x64 16KB tile blocks,
// interleaved: block 2t = hi panel of base tile t, block 2t+1 = lo panel.
__device__ __align__(256) __nv_bfloat16 g_pano_b[(size_t)BNr * K2D];
__device__ __align__(256) __nv_bfloat16 g_s_b [(size_t)BSr * K2D];
__device__ __align__(256) __nv_bfloat16 g_upd_b[(size_t)BSr * K2D];
__device__ __align__(256) __nv_bfloat16 g_h_b [(size_t)BSr * K2F];
__device__ __align__(256) __nv_bfloat16 g_pre_b[(size_t)BSr * K2F];
__device__ __align__(256) __nv_bfloat16 g_hid_b[(size_t)BSr * K2D];
__device__ __align__(256) __nv_bfloat16 g_wq_b [(size_t)2176 * K2D];
__device__ __align__(256) __nv_bfloat16 g_wk_b [(size_t)2176 * K2D];
__device__ __align__(256) __nv_bfloat16 g_wv_b [(size_t)2176 * K2D];
__device__ __align__(256) __nv_bfloat16 g_wih_b[(size_t)6144 * K2D];
__device__ __align__(256) __nv_bfloat16 g_whh_b[(size_t)6144 * K2F];
__device__ __align__(256) __nv_bfloat16 g_w1_b [(size_t)2176 * K2F];
__device__ __align__(256) __nv_bfloat16 g_w2_b [(size_t)2048 * K2D];

__device__ __forceinline__ uint32_t smem_u32(const void* p) {
    uint32_t a;
    asm("{ .reg .u64 t; cvta.to.shared.u64 t, %1; cvt.u32.u64 %0, t; }" : "=r"(a) : "l"(p));
    return a;
}
#define MBAR_INIT(a, c) asm volatile("mbarrier.init.shared.b64 [%0], %1;" :: "r"(a), "r"(c) : "memory")
#define MBAR_EXPECT_TX(a, b) asm volatile("mbarrier.arrive.expect_tx.shared.b64 _, [%0], %1;" :: "r"(a), "r"(b) : "memory")
#define MBAR_WAIT(a, p) do { \
    uint32_t _m = (a), _p = (p), _d; \
    asm volatile("{\n\t.reg .pred q;\n\tmbarrier.try_wait.parity.acquire.cta.shared::cta.b64 q, [%1], %2;\n\tselp.b32 %0, 1, 0, q;\n\t}" \
        : "=r"(_d) : "r"(_m), "r"(_p) : "memory"); \
    if (!_d) { \
        asm volatile("{\n\t.reg .pred P1;\n\tWL_%=:\n\tmbarrier.try_wait.parity.acquire.cta.shared::cta.b64 P1, [%0], %1, 0x989680;\n\t@P1 bra.uni WD_%=;\n\tbra.uni WL_%=;\n\tWD_%=:\n\t}" \
            :: "r"(_m), "r"(_p) : "memory"); \
    } } while (0)

__device__ __forceinline__ void bulk_g2s(uint32_t dst, const void* src, uint32_t bytes, uint32_t mbar) {
    asm volatile("cp.async.bulk.shared::cluster.global.mbarrier::complete_tx::bytes [%0], [%1], %2, [%3];"
        :: "r"(dst), "l"(src), "r"(bytes), "r"(mbar) : "memory");
}

__device__ __forceinline__ uint32_t packbf(float a, float b) {
    return (uint32_t)__bfloat16_as_ushort(__float2bfloat16_rn(a)) |
           ((uint32_t)__bfloat16_as_ushort(__float2bfloat16_rn(b)) << 16);
}
__device__ __forceinline__ float residf(float a) {
    return a - __bfloat162float(__float2bfloat16_rn(a));
}
__device__ __forceinline__ uint32_t swz(uint32_t o) { return o ^ ((o >> 3) & 0x70); }
// write hi+lo pair (cols col,col+1) of row r in row-panel rb; kt2 blocks per panel
__device__ __forceinline__ void put2(char* base, int rb, int kt2, int r, int col,
                                     uint32_t hi, uint32_t lo) {
    const int t = col >> 6, cc = col & 63;
    char* p = base + (((size_t)rb * kt2 + 2 * t) << 14) + swz(((uint32_t)r << 7) + ((uint32_t)cc << 1));
    *(uint32_t*)p = hi;
    *(uint32_t*)(p + 16384) = lo;
}

__global__ void detect_mask_k(const unsigned char* __restrict__ m) {
    __shared__ int c1, c3f;
    if (threadIdx.x == 0) { c1 = 0; c3f = 0; }
    __syncthreads();
    int l1 = 0, l3 = 0;
    for (int i = threadIdx.x; i < BSr; i += 256) {
        unsigned char v = m[i];
        if ((i & 3) != 0 && v == 1) l1++;
        if (v == 0x3f) l3++;
    }
    atomicAdd(&c1, l1); atomicAdd(&c3f, l3);
    __syncthreads();
    if (threadIdx.x == 0) g_mask_mode = (c3f > 0) ? 2 : (c1 > 0 ? 0 : 1);
}

// LN over cF cols of x (stride xs); cols [cF,Kx) from tailsrc (stride cD).
template <bool TAIL>
__global__ void __launch_bounds__(256) ln_bf16_k(
    const float* __restrict__ x, int xs, const float* __restrict__ tailsrc,
    const float* __restrict__ gam, const float* __restrict__ bet,
    __nv_bfloat16* __restrict__ dst, int Kx, int kt2)
{
    const int row = blockIdx.x, tid = threadIdx.x;
    const float* xr = x + (size_t)row * xs;
    float s = 0.f, s2 = 0.f;
    for (int c = tid * 4; c < cF; c += 1024) {
        float4 v = *reinterpret_cast<const float4*>(xr + c);
        s += v.x + v.y + v.z + v.w;
        s2 += v.x * v.x + v.y * v.y + v.z * v.z + v.w * v.w;
    }
    #pragma unroll
    for (int o = 16; o; o >>= 1) {
        s += __shfl_xor_sync(0xffffffffu, s, o);
        s2 += __shfl_xor_sync(0xffffffffu, s2, o);
    }
    __shared__ float ws[8], ws2[8];
    const int warp = tid >> 5, lane = tid & 31;
    if (lane == 0) { ws[warp] = s; ws2[warp] = s2; }
    __syncthreads();
    if (tid == 0) {
        float a = 0.f, b2 = 0.f;
        #pragma unroll
        for (int w = 0; w < 8; w++) { a += ws[w]; b2 += ws2[w]; }
        ws[0] = a; ws2[0] = b2;
    }
    __syncthreads();
    const float mean = ws[0] * (1.f / cF);
    const float rstd = rsqrtf(ws2[0] * (1.f / cF) - mean * mean + 1e-5f);
    const int mt = row >> 7, r = row & 127;
    char* db = (char*)dst;
    for (int p = tid; p < (Kx >> 1); p += 256) {
        const int c = 2 * p;
        float a, b;
        if (c < cF) {
            a = (xr[c] - mean) * rstd * gam[c] + bet[c];
            b = (xr[c + 1] - mean) * rstd * gam[c + 1] + bet[c + 1];
        } else {
            a = TAIL ? tailsrc[(size_t)row * cD + c] : 0.f;
            b = TAIL ? tailsrc[(size_t)row * cD + c + 1] : 0.f;
        }
        put2(db, mt, kt2, r, c, packbf(a, b), packbf(residf(a), residf(b)));
    }
}

__global__ void __launch_bounds__(256) conv_act_k(
    const float* __restrict__ x, int xs, __nv_bfloat16* __restrict__ dst, int Kx, int kt2)
{
    const int Kh = Kx >> 1;
    const size_t idx = (size_t)blockIdx.x * 256 + threadIdx.x;
    const int row = (int)(idx / Kh), c = 2 * (int)(idx % Kh);
    const float a = x[(size_t)row * xs + c], b = x[(size_t)row * xs + c + 1];
    put2((char*)dst, row >> 7, kt2, row & 127, c, packbf(a, b), packbf(residf(a), residf(b)));
}

__global__ void __launch_bounds__(256) conv_w_k(
    const float* __restrict__ w, __nv_bfloat16* __restrict__ dst, int Kx, int kt2)
{
    const int Kh = Kx >> 1;
    const size_t idx = (size_t)blockIdx.x * 256 + threadIdx.x;
    const int row = (int)(idx / Kh), c = 2 * (int)(idx % Kh);
    const float a = w[(size_t)row * Kx + c], b = w[(size_t)row * Kx + c + 1];
    put2((char*)dst, row >> 7, kt2, row & 127, c, packbf(a, b), packbf(residf(a), residf(b)));
}

// mma.sync GEMM with panel dedup: per base k-tile, load Ah,Al (32KB) + Wh,Wl (32KB),
// run 3 sub-passes (Ah*Wh, Ah*Wl, Al*Wh). BM=BN=128, 8 warps, 3-stage pipeline.
// SPLIT: 0 = fp32 C only; 1 = split-blocks only (W1+relu); 2 = fp32 C and split (W2+add).
constexpr int STG = 65536, SD0 = 1024, SMB = SD0 + 3 * STG;

template <bool RELU, bool ADD, int SPLIT>
__global__ void __launch_bounds__(256, 1) gemm_mma(
    const __nv_bfloat16* __restrict__ Ab, const __nv_bfloat16* __restrict__ Wb,
    const float* __restrict__ bias, const float* __restrict__ addsrc,
    float* __restrict__ C, int ktiles, int Nc,
    __nv_bfloat16* __restrict__ sdst, int skt2)
{
    extern __shared__ __align__(1024) char smem[];
    const uint32_t sb = smem_u32(smem);
    const int tid = threadIdx.x, warp = tid >> 5, lane = tid & 31;
    const int nt = blockIdx.x, mt = blockIdx.y;

    if (tid == 0) {
        #pragma unroll
        for (int s = 0; s < 3; s++) MBAR_INIT(sb + 8 * s, 1);
    }
    __syncthreads();

    const char* Ag = (const char*)Ab + (size_t)mt * ktiles * 32768;
    const char* Wg = (const char*)Wb + (size_t)nt * ktiles * 32768;

    if (tid == 0) {
        #pragma unroll
        for (int s = 0; s < 3; s++) {
            MBAR_EXPECT_TX(sb + 8 * s, 65536);
            bulk_g2s(sb + SD0 + s * STG, Ag + (size_t)s * 32768, 32768, sb + 8 * s);
            bulk_g2s(sb + SD0 + s * STG + 32768, Wg + (size_t)s * 32768, 32768, sb + 8 * s);
        }
    }

    const int m0w = (warp >> 1) << 5;                 // 0,32,64,96
    const int n0w = (warp & 1) << 6;                  // 0,64
    const int arow = m0w + (lane & 15);
    const uint32_t aoff0 = (uint32_t)arow << 7;
    const uint32_t axor = (uint32_t)(arow & 7) << 4;
    const uint32_t akh = (uint32_t)(lane >> 4) << 4;
    const uint32_t boff0 = (uint32_t)(n0w + lane) << 7;
    const uint32_t bxor = (uint32_t)(lane & 7) << 4;

    float acc[2][8][4];
    #pragma unroll
    for (int i = 0; i < 2; i++)
        #pragma unroll
        for (int j = 0; j < 8; j++)
            #pragma unroll
            for (int q = 0; q < 4; q++) acc[i][j][q] = 0.f;

    int s = 0, ph = 0;
    #pragma unroll 1
    for (int kt = 0; kt < ktiles; kt++) {
        MBAR_WAIT(sb + 8 * s, ph);
        const uint32_t stg = sb + SD0 + s * STG;
        #pragma unroll
        for (int pass = 0; pass < 3; pass++) {
            const uint32_t As = stg + ((pass == 2) ? 16384u : 0u);
            const uint32_t Bs = stg + 32768u + ((pass == 1) ? 16384u : 0u);
            #pragma unroll
            for (int kk = 0; kk < 4; kk++) {
                uint32_t a[2][4];
                const uint32_t kbA = ((kk << 5) | akh) ^ axor;
                #pragma unroll
                for (int im = 0; im < 2; im++) {
                    uint32_t ad = As + aoff0 + (im << 11) + kbA;
                    asm volatile("ldmatrix.sync.aligned.m8n8.x4.shared.b16 {%0,%1,%2,%3}, [%4];"
                        : "=r"(a[im][0]), "=r"(a[im][1]), "=r"(a[im][2]), "=r"(a[im][3]) : "r"(ad));
                }
                uint32_t b0[8], b1[8];
                #pragma unroll
                for (int q = 0; q < 2; q++) {
                    uint32_t bd = Bs + boff0 + (q << 12);
                    uint32_t k0 = (kk << 5) ^ bxor;
                    uint32_t k1 = ((kk << 5) | 16) ^ bxor;
                    asm volatile("ldmatrix.sync.aligned.m8n8.x4.shared.b16 {%0,%1,%2,%3}, [%4];"
                        : "=r"(b0[q*4+0]), "=r"(b0[q*4+1]), "=r"(b0[q*4+2]), "=r"(b0[q*4+3]) : "r"(bd + k0));
                    asm volatile("ldmatrix.sync.aligned.m8n8.x4.shared.b16 {%0,%1,%2,%3}, [%4];"
                        : "=r"(b1[q*4+0]), "=r"(b1[q*4+1]), "=r"(b1[q*4+2]), "=r"(b1[q*4+3]) : "r"(bd + k1));
                }
                #pragma unroll
                for (int im = 0; im < 2; im++)
                    #pragma unroll
                    for (int ng = 0; ng < 8; ng++)
                        asm volatile("mma.sync.aligned.m16n8k16.row.col.f32.bf16.bf16.f32 "
                            "{%0,%1,%2,%3}, {%4,%5,%6,%7}, {%8,%9}, {%0,%1,%2,%3};"
                            : "+f"(acc[im][ng][0]), "+f"(acc[im][ng][1]),
                              "+f"(acc[im][ng][2]), "+f"(acc[im][ng][3])
                            : "r"(a[im][0]), "r"(a[im][1]), "r"(a[im][2]), "r"(a[im][3]),
                              "r"(b0[ng]), "r"(b1[ng]));
            }
        }
        __syncthreads();
        if (tid == 0 && kt + 3 < ktiles) {
            MBAR_EXPECT_TX(sb + 8 * s, 65536);
            bulk_g2s(sb + SD0 + s * STG, Ag + (size_t)(kt + 3) * 32768, 32768, sb + 8 * s);
            bulk_g2s(sb + SD0 + s * STG + 32768, Wg + (size_t)(kt + 3) * 32768, 32768, sb + 8 * s);
        }
        if (++s == 3) { s = 0; ph ^= 1; }
    }

    const int rb = mt * 128 + m0w + (lane >> 2);
    const int cb = nt * 128 + n0w + ((lane & 3) << 1);
    #pragma unroll
    for (int im = 0; im < 2; im++) {
        #pragma unroll
        for (int ng = 0; ng < 8; ng++) {
            const int r0 = rb + im * 16, c = cb + ng * 8;
            const float bx = bias[c], by = bias[c + 1];
            float2 v0 = make_float2(acc[im][ng][0] + bx, acc[im][ng][1] + by);
            float2 v1 = make_float2(acc[im][ng][2] + bx, acc[im][ng][3] + by);
            if (RELU) {
                v0.x = fmaxf(v0.x, 0.f); v0.y = fmaxf(v0.y, 0.f);
                v1.x = fmaxf(v1.x, 0.f); v1.y = fmaxf(v1.y, 0.f);
            }
            if (ADD) {
                const float2 a0 = *(const float2*)(addsrc + (size_t)r0 * Nc + c);
                const float2 a1 = *(const float2*)(addsrc + (size_t)(r0 + 8) * Nc + c);
                v0.x += a0.x; v0.y += a0.y; v1.x += a1.x; v1.y += a1.y;
            }
            if (SPLIT != 1) {
                *(float2*)(C + (size_t)r0 * Nc + c) = v0;
                *(float2*)(C + (size_t)(r0 + 8) * Nc + c) = v1;
            }
            if (SPLIT != 0) {
                put2((char*)sdst, r0 >> 7, skt2, r0 & 127, c,
                     packbf(v0.x, v0.y), packbf(residf(v0.x), residf(v0.y)));
                put2((char*)sdst, (r0 + 8) >> 7, skt2, (r0 + 8) & 127, c,
                     packbf(v1.x, v1.y), packbf(residf(v1.x), residf(v1.y)));
            }
        }
    }
}

// attention: dots -> masked softmax(axis=i) -> attn @ v, writing split upd blocks
__global__ void __launch_bounds__(256) attn_k(
    const void* __restrict__ mask, const float* __restrict__ q,
    const float* __restrict__ kk, const float* __restrict__ vv,
    float* __restrict__ attn_out, __nv_bfloat16* __restrict__ upd_b)
{
    const int b = blockIdx.x;
    __shared__ float sd[cS][cN];
    __shared__ float smask[cS];
    const int tid = threadIdx.x;
    if (tid < cS) {
        const int mm = g_mask_mode;
        const int idx = b * cS + tid;
        bool mk;
        if (mm == 0)      mk = ((const unsigned char*)mask)[idx] != 0;
        else if (mm == 1) mk = ((const int*)mask)[idx] != 0;
        else              mk = ((const float*)mask)[idx] != 0.f;
        smask[tid] = mk ? 1.f : 0.f;
    }
    __syncthreads();
    const int warp = tid >> 5, lane = tid & 31;
    const float scale = rsqrtf((float)cD);
    for (int p = warp; p < cS * cN; p += 8) {
        const int i = p / cN, j = p % cN;
        const float* qr = q + (size_t)(b * cS + i) * cD;
        const float* kr = kk + (size_t)(b * cN + j) * cD;
        float sum = 0.f;
        for (int d = lane * 4; d < cD; d += 128) {
            float4 qa = *reinterpret_cast<const float4*>(qr + d);
            float4 ka = *reinterpret_cast<const float4*>(kr + d);
            sum += qa.x * ka.x + qa.y * ka.y + qa.z * ka.z + qa.w * ka.w;
        }
        #pragma unroll
        for (int o = 16; o; o >>= 1) sum += __shfl_xor_sync(0xffffffffu, sum, o);
        if (lane == 0) sd[i][j] = (smask[i] > 0.f) ? -INFINITY : sum * scale;
    }
    __syncthreads();
    if (tid < cN) {
        const int j = tid;
        float m = -INFINITY;
        #pragma unroll
        for (int i = 0; i < cS; i++) m = fmaxf(m, sd[i][j]);
        float e[cS], ssum = 0.f;
        #pragma unroll
        for (int i = 0; i < cS; i++) { e[i] = expf(sd[i][j] - m); ssum += e[i]; }
        const float inv = 1.f / ssum;
        #pragma unroll
        for (int i = 0; i < cS; i++) {
            const float a = e[i] * inv;
            sd[i][j] = a;
            attn_out[(size_t)(b * cS + i) * cN + j] = a;
        }
    }
    __syncthreads();
    for (int d = tid * 2; d < cD; d += 512) {
        float a0[cS], a1[cS];
        #pragma unroll
        for (int i = 0; i < cS; i++) { a0[i] = 0.f; a1[i] = 0.f; }
        for (int j = 0; j < cN; j++) {
            const float2 vj = *(const float2*)(vv + (size_t)(b * cN + j) * cD + d);
            #pragma unroll
            for (int i = 0; i < cS; i++) {
                a0[i] = fmaf(sd[i][j], vj.x, a0[i]);
                a1[i] = fmaf(sd[i][j], vj.y, a1[i]);
            }
        }
        #pragma unroll
        for (int i = 0; i < cS; i++) {
            const int row = b * cS + i;
            put2((char*)upd_b, row >> 7, KT2D, row & 127, d,
                 packbf(a0[i], a1[i]), packbf(residf(a0[i]), residf(a1[i])));
        }
    }
}

__global__ void __launch_bounds__(256) gru_k(
    const float* __restrict__ gi, const float* __restrict__ gh,
    const float* __restrict__ h, float* __restrict__ hnew)
{
    const size_t idx = (size_t)blockIdx.x * 256 + threadIdx.x;
    const int row = (int)(idx / cF), f = (int)(idx % cF);
    const size_t o = (size_t)row * G3 + f;
    const float ir = gi[o], iz = gi[o + cF], inn = gi[o + 2 * cF];
    const float hr = gh[o], hz = gh[o + cF], hn = gh[o + 2 * cF];
    const float hp = h[(size_t)row * cF + f];
    const float r = 1.f / (1.f + expf(-(ir + hr)));
    const float z = 1.f / (1.f + expf(-(iz + hz)));
    const float n = tanhf(inn + r * hn);
    hnew[(size_t)row * cF + f] = (1.f - z) * n + z * hp;
}

__global__ void __launch_bounds__(256) init_h_k(const float* __restrict__ cand, float* __restrict__ h) {
    const size_t idx = (size_t)blockIdx.x * 256 + threadIdx.x;
    const int row = (int)(idx / cF), f = (int)(idx % cF);
    h[idx] = cand[(size_t)row * cD + f];
}
__global__ void __launch_bounds__(256) out_slots_k(
    const float* __restrict__ cand, const float* __restrict__ h, float* __restrict__ out) {
    const size_t idx = (size_t)blockIdx.x * 256 + threadIdx.x;
    const int row = (int)(idx / cD), c = (int)(idx % cD);
    out[idx] = (c < cF) ? h[(size_t)row * cF + c] : cand[idx];
}
__global__ void __launch_bounds__(256) out_attn_k(const float* __restrict__ attn, float* __restrict__ out) {
    const size_t idx = (size_t)blockIdx.x * 256 + threadIdx.x;
    out[(size_t)BSr * cD + idx] = attn[idx];
}

extern "C" void kernel_launch(void* const* d_in, const int* in_sizes, int n_in,
                              void* d_out, int out_size)
{
    const float* cand = (const float*)d_in[0];
    const float* pano = (const float*)d_in[1];
    const void* mask = d_in[2];
    const float* Wq = (const float*)d_in[3];
    const float* bq = (const float*)d_in[4];
    const float* Wk = (const float*)d_in[5];
    const float* bk = (const float*)d_in[6];
    const float* Wv = (const float*)d_in[7];
    const float* bv = (const float*)d_in[8];
    const float* W_ih = (const float*)d_in[9];
    const float* b_ih = (const float*)d_in[10];
    const float* W_hh = (const float*)d_in[11];
    const float* b_hh = (const float*)d_in[12];
    const float* W1 = (const float*)d_in[13];
    const float* b1 = (const float*)d_in[14];
    const float* W2 = (const float*)d_in[15];
    const float* b2 = (const float*)d_in[16];
    const float* ln_in_g = (const float*)d_in[17];
    const float* ln_in_b = (const float*)d_in[18];
    const float* ln_slots_g = (const float*)d_in[19];
    const float* ln_slots_b = (const float*)d_in[20];
    const float* ln_pre_g = (const float*)d_in[21];
    const float* ln_pre_b = (const float*)d_in[22];
    float* out = (float*)d_out;

    float *p_k, *p_v, *p_q, *p_gi, *p_gh, *p_h, *p_hnew, *p_attn;
    __nv_bfloat16 *b_pano, *b_s, *b_upd, *b_h, *b_pre, *b_hid;
    __nv_bfloat16 *b_wq, *b_wk, *b_wv, *b_wih, *b_whh, *b_w1, *b_w2;
    cudaGetSymbolAddress((void**)&p_k, g_k);
    cudaGetSymbolAddress((void**)&p_v, g_v);
    cudaGetSymbolAddress((void**)&p_q, g_q);
    cudaGetSymbolAddress((void**)&p_gi, g_gi);
    cudaGetSymbolAddress((void**)&p_gh, g_gh);
    cudaGetSymbolAddress((void**)&p_h, g_h);
    cudaGetSymbolAddress((void**)&p_hnew, g_hnew);
    cudaGetSymbolAddress((void**)&p_attn, g_attn);
    cudaGetSymbolAddress((void**)&b_pano, g_pano_b);
    cudaGetSymbolAddress((void**)&b_s, g_s_b);
    cudaGetSymbolAddress((void**)&b_upd, g_upd_b);
    cudaGetSymbolAddress((void**)&b_h, g_h_b);
    cudaGetSymbolAddress((void**)&b_pre, g_pre_b);
    cudaGetSymbolAddress((void**)&b_hid, g_hid_b);
    cudaGetSymbolAddress((void**)&b_wq, g_wq_b);
    cudaGetSymbolAddress((void**)&b_wk, g_wk_b);
    cudaGetSymbolAddress((void**)&b_wv, g_wv_b);
    cudaGetSymbolAddress((void**)&b_wih, g_wih_b);
    cudaGetSymbolAddress((void**)&b_whh, g_whh_b);
    cudaGetSymbolAddress((void**)&b_w1, g_w1_b);
    cudaGetSymbolAddress((void**)&b_w2, g_w2_b);

    cudaFuncSetAttribute(gemm_mma<false, false, 0>, cudaFuncAttributeMaxDynamicSharedMemorySize, SMB);
    cudaFuncSetAttribute(gemm_mma<true, false, 1>, cudaFuncAttributeMaxDynamicSharedMemorySize, SMB);
    cudaFuncSetAttribute(gemm_mma<false, true, 2>, cudaFuncAttributeMaxDynamicSharedMemorySize, SMB);

    detect_mask_k<<<1, 256>>>((const unsigned char*)mask);

    // weight conversions ([hi|lo] interleaved blocks)
    conv_w_k<<<(2176 * 1088) / 256, 256>>>(Wq, b_wq, 2176, KT2D);
    conv_w_k<<<(2176 * 1088) / 256, 256>>>(Wk, b_wk, 2176, KT2D);
    conv_w_k<<<(2176 * 1088) / 256, 256>>>(Wv, b_wv, 2176, KT2D);
    conv_w_k<<<(6144 * 1088) / 256, 256>>>(W_ih, b_wih, 2176, KT2D);
    conv_w_k<<<(6144 * 1024) / 256, 256>>>(W_hh, b_whh, 2048, KT2F);
    conv_w_k<<<(2176 * 1024) / 256, 256>>>(W1, b_w1, 2048, KT2F);
    conv_w_k<<<(2048 * 1088) / 256, 256>>>(W2, b_w2, 2176, KT2D);

    ln_bf16_k<true><<<BNr, 256>>>(pano, cD, pano, ln_in_g, ln_in_b, b_pano, 2176, KT2D);
    gemm_mma<false, false, 0><<<dim3(17, 288), 256, SMB>>>(b_pano, b_wk, bk, nullptr, p_k, KTD, 2176, nullptr, 0);
    gemm_mma<false, false, 0><<<dim3(17, 288), 256, SMB>>>(b_pano, b_wv, bv, nullptr, p_v, KTD, 2176, nullptr, 0);

    init_h_k<<<(BSr * cF) / 256, 256>>>(cand, p_h);
    conv_act_k<<<(BSr * 1024) / 256, 256>>>(p_h, cF, b_h, 2048, KT2F);

    for (int it = 0; it < 3; it++) {
        ln_bf16_k<true><<<BSr, 256>>>(p_h, cF, cand, ln_slots_g, ln_slots_b, b_s, 2176, KT2D);
        gemm_mma<false, false, 0><<<dim3(17, 80), 256, SMB>>>(b_s, b_wq, bq, nullptr, p_q, KTD, 2176, nullptr, 0);
        attn_k<<<cB, 256>>>(mask, p_q, p_k, p_v, p_attn, b_upd);
        gemm_mma<false, false, 0><<<dim3(48, 80), 256, SMB>>>(b_upd, b_wih, b_ih, nullptr, p_gi, KTD, 6144, nullptr, 0);
        gemm_mma<false, false, 0><<<dim3(48, 80), 256, SMB>>>(b_h, b_whh, b_hh, nullptr, p_gh, KTF, 6144, nullptr, 0);
        gru_k<<<(BSr * cF) / 256, 256>>>(p_gi, p_gh, p_h, p_hnew);
        ln_bf16_k<false><<<BSr, 256>>>(p_hnew, cF, nullptr, ln_pre_g, ln_pre_b, b_pre, 2048, KT2F);
        gemm_mma<true, false, 1><<<dim3(17, 80), 256, SMB>>>(b_pre, b_w1, b1, nullptr, nullptr, KTF, 2176, b_hid, KT2D);
        gemm_mma<false, true, 2><<<dim3(16, 80), 256, SMB>>>(b_hid, b_w2, b2, p_hnew, p_h, KTD, 2048, b_h, KT2F);
    }

    out_slots_k<<<(BSr * cD) / 256, 256>>>(cand, p_h, out);
    out_attn_k<<<(BSr * cN) / 256, 256>>>(p_attn, out);
}

// round 7
// speedup vs baseline: 1.1224x; 1.1224x over previous
#include <cuda_runtime.h>
#include <cuda_bf16.h>
#include <math.h>
#include <stdint.h>

constexpr int cB = 1024, cS = 10, cN = 36, cF = 2048, cD = 2176;
constexpr int BSr = cB * cS, BNr = cB * cN, G3 = 3 * cF;
constexpr int K3D = 3 * cD, K3F = 3 * cF;        // 6528 / 6144
constexpr int KTD = K3D / 64, KTF = K3F / 64;    // 102 / 96 (total K' tiles)
constexpr int K1D = cD / 64, K1F = cF / 64;      // 34 / 32 (base k-tiles)

// fp32 scratch
__device__ float g_k[(size_t)BNr * cD];
__device__ float g_v[(size_t)BNr * cD];
__device__ float g_q[(size_t)BSr * cD];
__device__ float g_gi[(size_t)BSr * G3];
__device__ float g_gh[(size_t)BSr * G3];
__device__ float g_h[(size_t)BSr * cF];
__device__ float g_hnew[(size_t)BSr * cF];
__device__ float g_attn[(size_t)BSr * cN];
__device__ int g_mask_mode;

// bf16 split operands ([hi|hi|lo] for A, [hi|lo|hi] for W), pre-swizzled
// 128x64 16KB tile blocks.
__device__ __align__(256) __nv_bfloat16 g_pano_b[(size_t)BNr * K3D];
__device__ __align__(256) __nv_bfloat16 g_s_b [(size_t)BSr * K3D];
__device__ __align__(256) __nv_bfloat16 g_upd_b[(size_t)BSr * K3D];
__device__ __align__(256) __nv_bfloat16 g_h_b [(size_t)BSr * K3F];
__device__ __align__(256) __nv_bfloat16 g_pre_b[(size_t)BSr * K3F];
__device__ __align__(256) __nv_bfloat16 g_hid_b[(size_t)BSr * K3D];
__device__ __align__(256) __nv_bfloat16 g_wq_b [(size_t)2176 * K3D];
__device__ __align__(256) __nv_bfloat16 g_wk_b [(size_t)2176 * K3D];
__device__ __align__(256) __nv_bfloat16 g_wv_b [(size_t)2176 * K3D];
__device__ __align__(256) __nv_bfloat16 g_wih_b[(size_t)6144 * K3D];
__device__ __align__(256) __nv_bfloat16 g_whh_b[(size_t)6144 * K3F];
__device__ __align__(256) __nv_bfloat16 g_w1_b [(size_t)2176 * K3F];
__device__ __align__(256) __nv_bfloat16 g_w2_b [(size_t)2048 * K3D];

__device__ __forceinline__ uint32_t smem_u32(const void* p) {
    uint32_t a;
    asm("{ .reg .u64 t; cvta.to.shared.u64 t, %1; cvt.u32.u64 %0, t; }" : "=r"(a) : "l"(p));
    return a;
}
#define MBAR_INIT(a, c) asm volatile("mbarrier.init.shared.b64 [%0], %1;" :: "r"(a), "r"(c) : "memory")
#define MBAR_EXPECT_TX(a, b) asm volatile("mbarrier.arrive.expect_tx.shared.b64 _, [%0], %1;" :: "r"(a), "r"(b) : "memory")
#define MBAR_WAIT(a, p) do { \
    uint32_t _m = (a), _p = (p), _d; \
    asm volatile("{\n\t.reg .pred q;\n\tmbarrier.try_wait.parity.acquire.cta.shared::cta.b64 q, [%1], %2;\n\tselp.b32 %0, 1, 0, q;\n\t}" \
        : "=r"(_d) : "r"(_m), "r"(_p) : "memory"); \
    if (!_d) { \
        asm volatile("{\n\t.reg .pred P1;\n\tWL_%=:\n\tmbarrier.try_wait.parity.acquire.cta.shared::cta.b64 P1, [%0], %1, 0x989680;\n\t@P1 bra.uni WD_%=;\n\tbra.uni WL_%=;\n\tWD_%=:\n\t}" \
            :: "r"(_m), "r"(_p) : "memory"); \
    } } while (0)

__device__ __forceinline__ void bulk_g2s(uint32_t dst, const void* src, uint32_t bytes, uint32_t mbar) {
    asm volatile("cp.async.bulk.shared::cluster.global.mbarrier::complete_tx::bytes [%0], [%1], %2, [%3];"
        :: "r"(dst), "l"(src), "r"(bytes), "r"(mbar) : "memory");
}

__device__ __forceinline__ uint32_t packbf(float a, float b) {
    return (uint32_t)__bfloat16_as_ushort(__float2bfloat16_rn(a)) |
           ((uint32_t)__bfloat16_as_ushort(__float2bfloat16_rn(b)) << 16);
}
__device__ __forceinline__ float residf(float a) {
    return a - __bfloat162float(__float2bfloat16_rn(a));
}
__device__ __forceinline__ uint32_t swz(uint32_t o) { return o ^ ((o >> 3) & 0x70); }

// A-side split write: hi at block t, hi at t+kt1, lo at t+2*kt1 (kt1 = Kx/64)
__device__ __forceinline__ void put3a(char* base, int rb, int kt1, int r, int col,
                                      uint32_t hi, uint32_t lo) {
    const int t = col >> 6, cc = col & 63;
    const uint32_t so = swz(((uint32_t)r << 7) + ((uint32_t)cc << 1));
    char* p = base + (((size_t)rb * 3 * kt1 + t) << 14) + so;
    *(uint32_t*)p = hi;
    *(uint32_t*)(p + ((size_t)kt1 << 14)) = hi;
    *(uint32_t*)(p + ((size_t)(2 * kt1) << 14)) = lo;
}
// W-side split write: hi at t, lo at t+kt1, hi at t+2*kt1
__device__ __forceinline__ void put3w(char* base, int rb, int kt1, int r, int col,
                                      uint32_t hi, uint32_t lo) {
    const int t = col >> 6, cc = col & 63;
    const uint32_t so = swz(((uint32_t)r << 7) + ((uint32_t)cc << 1));
    char* p = base + (((size_t)rb * 3 * kt1 + t) << 14) + so;
    *(uint32_t*)p = hi;
    *(uint32_t*)(p + ((size_t)kt1 << 14)) = lo;
    *(uint32_t*)(p + ((size_t)(2 * kt1) << 14)) = hi;
}

__global__ void detect_mask_k(const unsigned char* __restrict__ m) {
    __shared__ int c1, c3f;
    if (threadIdx.x == 0) { c1 = 0; c3f = 0; }
    __syncthreads();
    int l1 = 0, l3 = 0;
    for (int i = threadIdx.x; i < BSr; i += 256) {
        unsigned char v = m[i];
        if ((i & 3) != 0 && v == 1) l1++;
        if (v == 0x3f) l3++;
    }
    atomicAdd(&c1, l1); atomicAdd(&c3f, l3);
    __syncthreads();
    if (threadIdx.x == 0) g_mask_mode = (c3f > 0) ? 2 : (c1 > 0 ? 0 : 1);
}

// LN over cF cols of x (stride xs); cols [cF,Kx) from tailsrc (stride cD).
template <bool TAIL>
__global__ void __launch_bounds__(256) ln_bf16_k(
    const float* __restrict__ x, int xs, const float* __restrict__ tailsrc,
    const float* __restrict__ gam, const float* __restrict__ bet,
    __nv_bfloat16* __restrict__ dst, int Kx, int kt1)
{
    const int row = blockIdx.x, tid = threadIdx.x;
    const float* xr = x + (size_t)row * xs;
    float s = 0.f, s2 = 0.f;
    for (int c = tid * 4; c < cF; c += 1024) {
        float4 v = *reinterpret_cast<const float4*>(xr + c);
        s += v.x + v.y + v.z + v.w;
        s2 += v.x * v.x + v.y * v.y + v.z * v.z + v.w * v.w;
    }
    #pragma unroll
    for (int o = 16; o; o >>= 1) {
        s += __shfl_xor_sync(0xffffffffu, s, o);
        s2 += __shfl_xor_sync(0xffffffffu, s2, o);
    }
    __shared__ float ws[8], ws2[8];
    const int warp = tid >> 5, lane = tid & 31;
    if (lane == 0) { ws[warp] = s; ws2[warp] = s2; }
    __syncthreads();
    if (tid == 0) {
        float a = 0.f, b2 = 0.f;
        #pragma unroll
        for (int w = 0; w < 8; w++) { a += ws[w]; b2 += ws2[w]; }
        ws[0] = a; ws2[0] = b2;
    }
    __syncthreads();
    const float mean = ws[0] * (1.f / cF);
    const float rstd = rsqrtf(ws2[0] * (1.f / cF) - mean * mean + 1e-5f);
    const int mt = row >> 7, r = row & 127;
    char* db = (char*)dst;
    for (int p = tid; p < (Kx >> 1); p += 256) {
        const int c = 2 * p;
        float a, b;
        if (c < cF) {
            a = (xr[c] - mean) * rstd * gam[c] + bet[c];
            b = (xr[c + 1] - mean) * rstd * gam[c + 1] + bet[c + 1];
        } else {
            a = TAIL ? tailsrc[(size_t)row * cD + c] : 0.f;
            b = TAIL ? tailsrc[(size_t)row * cD + c + 1] : 0.f;
        }
        put3a(db, mt, kt1, r, c, packbf(a, b), packbf(residf(a), residf(b)));
    }
}

__global__ void __launch_bounds__(256) conv_act_k(
    const float* __restrict__ x, int xs, __nv_bfloat16* __restrict__ dst, int Kx, int kt1)
{
    const int Kh = Kx >> 1;
    const size_t idx = (size_t)blockIdx.x * 256 + threadIdx.x;
    const int row = (int)(idx / Kh), c = 2 * (int)(idx % Kh);
    const float a = x[(size_t)row * xs + c], b = x[(size_t)row * xs + c + 1];
    put3a((char*)dst, row >> 7, kt1, row & 127, c, packbf(a, b), packbf(residf(a), residf(b)));
}

__global__ void __launch_bounds__(256) conv_w_k(
    const float* __restrict__ w, __nv_bfloat16* __restrict__ dst, int Kx, int kt1)
{
    const int Kh = Kx >> 1;
    const size_t idx = (size_t)blockIdx.x * 256 + threadIdx.x;
    const int row = (int)(idx / Kh), c = 2 * (int)(idx % Kh);
    const float a = w[(size_t)row * Kx + c], b = w[(size_t)row * Kx + c + 1];
    put3w((char*)dst, row >> 7, kt1, row & 127, c, packbf(a, b), packbf(residf(a), residf(b)));
}

// mma.sync GEMM: C[M,Nc] = A'[M,K'] @ W'[Nc,K']^T; BM=BN=128 BK=64,
// 8 warps (4x2), warp tile 32x64, 3-stage bulk pipeline, 2 CTA/SM.
// SPLIT: 0 = fp32 C only; 1 = split blocks only; 2 = fp32 C + split blocks.
constexpr int STG = 32768, SD0 = 1024, SMB = SD0 + 3 * STG;

template <bool RELU, bool ADD, int SPLIT>
__global__ void __launch_bounds__(256, 2) gemm_mma(
    const __nv_bfloat16* __restrict__ Ab, const __nv_bfloat16* __restrict__ Wb,
    const float* __restrict__ bias, const float* __restrict__ addsrc,
    float* __restrict__ C, int ktiles, int Nc,
    __nv_bfloat16* __restrict__ sdst, int skt1)
{
    extern __shared__ __align__(1024) char smem[];
    const uint32_t sb = smem_u32(smem);
    const int tid = threadIdx.x, warp = tid >> 5, lane = tid & 31;
    const int nt = blockIdx.x, mt = blockIdx.y;

    if (tid == 0) {
        #pragma unroll
        for (int s = 0; s < 3; s++) MBAR_INIT(sb + 8 * s, 1);
    }
    __syncthreads();

    const char* Ag = (const char*)Ab + (size_t)mt * ktiles * 16384;
    const char* Wg = (const char*)Wb + (size_t)nt * ktiles * 16384;

    if (tid == 0) {
        #pragma unroll
        for (int s = 0; s < 3; s++) {
            MBAR_EXPECT_TX(sb + 8 * s, 32768);
            bulk_g2s(sb + SD0 + s * STG, Ag + (size_t)s * 16384, 16384, sb + 8 * s);
            bulk_g2s(sb + SD0 + s * STG + 16384, Wg + (size_t)s * 16384, 16384, sb + 8 * s);
        }
    }

    const int m0w = (warp >> 1) << 5;
    const int n0w = (warp & 1) << 6;
    const int arow = m0w + (lane & 15);
    const uint32_t aoff0 = (uint32_t)arow << 7;
    const uint32_t axor = (uint32_t)(arow & 7) << 4;
    const uint32_t akh = (uint32_t)(lane >> 4) << 4;
    const uint32_t boff0 = (uint32_t)(n0w + lane) << 7;
    const uint32_t bxor = (uint32_t)(lane & 7) << 4;

    float acc[2][8][4];
    #pragma unroll
    for (int i = 0; i < 2; i++)
        #pragma unroll
        for (int j = 0; j < 8; j++)
            #pragma unroll
            for (int q = 0; q < 4; q++) acc[i][j][q] = 0.f;

    int s = 0, ph = 0;
    #pragma unroll 1
    for (int kt = 0; kt < ktiles; kt++) {
        MBAR_WAIT(sb + 8 * s, ph);
        const uint32_t As = sb + SD0 + s * STG;
        const uint32_t Bs = As + 16384;
        #pragma unroll
        for (int kk = 0; kk < 4; kk++) {
            uint32_t a[2][4];
            const uint32_t kbA = ((kk << 5) | akh) ^ axor;
            #pragma unroll
            for (int im = 0; im < 2; im++) {
                uint32_t ad = As + aoff0 + (im << 11) + kbA;
                asm volatile("ldmatrix.sync.aligned.m8n8.x4.shared.b16 {%0,%1,%2,%3}, [%4];"
                    : "=r"(a[im][0]), "=r"(a[im][1]), "=r"(a[im][2]), "=r"(a[im][3]) : "r"(ad));
            }
            uint32_t b0[8], b1[8];
            #pragma unroll
            for (int q = 0; q < 2; q++) {
                uint32_t bd = Bs + boff0 + (q << 12);
                uint32_t k0 = (kk << 5) ^ bxor;
                uint32_t k1 = ((kk << 5) | 16) ^ bxor;
                asm volatile("ldmatrix.sync.aligned.m8n8.x4.shared.b16 {%0,%1,%2,%3}, [%4];"
                    : "=r"(b0[q*4+0]), "=r"(b0[q*4+1]), "=r"(b0[q*4+2]), "=r"(b0[q*4+3]) : "r"(bd + k0));
                asm volatile("ldmatrix.sync.aligned.m8n8.x4.shared.b16 {%0,%1,%2,%3}, [%4];"
                    : "=r"(b1[q*4+0]), "=r"(b1[q*4+1]), "=r"(b1[q*4+2]), "=r"(b1[q*4+3]) : "r"(bd + k1));
            }
            #pragma unroll
            for (int im = 0; im < 2; im++)
                #pragma unroll
                for (int ng = 0; ng < 8; ng++)
                    asm volatile("mma.sync.aligned.m16n8k16.row.col.f32.bf16.bf16.f32 "
                        "{%0,%1,%2,%3}, {%4,%5,%6,%7}, {%8,%9}, {%0,%1,%2,%3};"
                        : "+f"(acc[im][ng][0]), "+f"(acc[im][ng][1]),
                          "+f"(acc[im][ng][2]), "+f"(acc[im][ng][3])
                        : "r"(a[im][0]), "r"(a[im][1]), "r"(a[im][2]), "r"(a[im][3]),
                          "r"(b0[ng]), "r"(b1[ng]));
        }
        __syncthreads();
        if (tid == 0 && kt + 3 < ktiles) {
            MBAR_EXPECT_TX(sb + 8 * s, 32768);
            bulk_g2s(sb + SD0 + s * STG, Ag + (size_t)(kt + 3) * 16384, 16384, sb + 8 * s);
            bulk_g2s(sb + SD0 + s * STG + 16384, Wg + (size_t)(kt + 3) * 16384, 16384, sb + 8 * s);
        }
        if (++s == 3) { s = 0; ph ^= 1; }
    }

    const int rb = mt * 128 + m0w + (lane >> 2);
    const int cb = nt * 128 + n0w + ((lane & 3) << 1);
    #pragma unroll
    for (int im = 0; im < 2; im++) {
        #pragma unroll
        for (int ng = 0; ng < 8; ng++) {
            const int r0 = rb + im * 16, c = cb + ng * 8;
            const float bx = bias[c], by = bias[c + 1];
            float2 v0 = make_float2(acc[im][ng][0] + bx, acc[im][ng][1] + by);
            float2 v1 = make_float2(acc[im][ng][2] + bx, acc[im][ng][3] + by);
            if (RELU) {
                v0.x = fmaxf(v0.x, 0.f); v0.y = fmaxf(v0.y, 0.f);
                v1.x = fmaxf(v1.x, 0.f); v1.y = fmaxf(v1.y, 0.f);
            }
            if (ADD) {
                const float2 a0 = *(const float2*)(addsrc + (size_t)r0 * Nc + c);
                const float2 a1 = *(const float2*)(addsrc + (size_t)(r0 + 8) * Nc + c);
                v0.x += a0.x; v0.y += a0.y; v1.x += a1.x; v1.y += a1.y;
            }
            if (SPLIT != 1) {
                *(float2*)(C + (size_t)r0 * Nc + c) = v0;
                *(float2*)(C + (size_t)(r0 + 8) * Nc + c) = v1;
            }
            if (SPLIT != 0) {
                put3a((char*)sdst, r0 >> 7, skt1, r0 & 127, c,
                      packbf(v0.x, v0.y), packbf(residf(v0.x), residf(v0.y)));
                put3a((char*)sdst, (r0 + 8) >> 7, skt1, (r0 + 8) & 127, c,
                      packbf(v1.x, v1.y), packbf(residf(v1.x), residf(v1.y)));
            }
        }
    }
}

// attention: dots -> masked softmax(axis=i) -> attn @ v, writes split upd blocks
__global__ void __launch_bounds__(256) attn_k(
    const void* __restrict__ mask, const float* __restrict__ q,
    const float* __restrict__ kk, const float* __restrict__ vv,
    float* __restrict__ attn_out, __nv_bfloat16* __restrict__ upd_b)
{
    const int b = blockIdx.x;
    __shared__ float sd[cS][cN];
    __shared__ float smask[cS];
    const int tid = threadIdx.x;
    if (tid < cS) {
        const int mm = g_mask_mode;
        const int idx = b * cS + tid;
        bool mk;
        if (mm == 0)      mk = ((const unsigned char*)mask)[idx] != 0;
        else if (mm == 1) mk = ((const int*)mask)[idx] != 0;
        else              mk = ((const float*)mask)[idx] != 0.f;
        smask[tid] = mk ? 1.f : 0.f;
    }
    __syncthreads();
    const int warp = tid >> 5, lane = tid & 31;
    const float scale = rsqrtf((float)cD);
    for (int p = warp; p < cS * cN; p += 8) {
        const int i = p / cN, j = p % cN;
        const float* qr = q + (size_t)(b * cS + i) * cD;
        const float* kr = kk + (size_t)(b * cN + j) * cD;
        float sum = 0.f;
        for (int d = lane * 4; d < cD; d += 128) {
            float4 qa = *reinterpret_cast<const float4*>(qr + d);
            float4 ka = *reinterpret_cast<const float4*>(kr + d);
            sum += qa.x * ka.x + qa.y * ka.y + qa.z * ka.z + qa.w * ka.w;
        }
        #pragma unroll
        for (int o = 16; o; o >>= 1) sum += __shfl_xor_sync(0xffffffffu, sum, o);
        if (lane == 0) sd[i][j] = (smask[i] > 0.f) ? -INFINITY : sum * scale;
    }
    __syncthreads();
    if (tid < cN) {
        const int j = tid;
        float m = -INFINITY;
        #pragma unroll
        for (int i = 0; i < cS; i++) m = fmaxf(m, sd[i][j]);
        float e[cS], ssum = 0.f;
        #pragma unroll
        for (int i = 0; i < cS; i++) { e[i] = expf(sd[i][j] - m); ssum += e[i]; }
        const float inv = 1.f / ssum;
        #pragma unroll
        for (int i = 0; i < cS; i++) {
            const float a = e[i] * inv;
            sd[i][j] = a;
            attn_out[(size_t)(b * cS + i) * cN + j] = a;
        }
    }
    __syncthreads();
    for (int d = tid * 2; d < cD; d += 512) {
        float a0[cS], a1[cS];
        #pragma unroll
        for (int i = 0; i < cS; i++) { a0[i] = 0.f; a1[i] = 0.f; }
        for (int j = 0; j < cN; j++) {
            const float2 vj = *(const float2*)(vv + (size_t)(b * cN + j) * cD + d);
            #pragma unroll
            for (int i = 0; i < cS; i++) {
                a0[i] = fmaf(sd[i][j], vj.x, a0[i]);
                a1[i] = fmaf(sd[i][j], vj.y, a1[i]);
            }
        }
        #pragma unroll
        for (int i = 0; i < cS; i++) {
            const int row = b * cS + i;
            put3a((char*)upd_b, row >> 7, K1D, row & 127, d,
                  packbf(a0[i], a1[i]), packbf(residf(a0[i]), residf(a1[i])));
        }
    }
}

__global__ void __launch_bounds__(256) gru_k(
    const float* __restrict__ gi, const float* __restrict__ gh,
    const float* __restrict__ h, float* __restrict__ hnew)
{
    const size_t idx = (size_t)blockIdx.x * 256 + threadIdx.x;
    const int row = (int)(idx / cF), f = (int)(idx % cF);
    const size_t o = (size_t)row * G3 + f;
    const float ir = gi[o], iz = gi[o + cF], inn = gi[o + 2 * cF];
    const float hr = gh[o], hz = gh[o + cF], hn = gh[o + 2 * cF];
    const float hp = h[(size_t)row * cF + f];
    const float r = 1.f / (1.f + expf(-(ir + hr)));
    const float z = 1.f / (1.f + expf(-(iz + hz)));
    const float n = tanhf(inn + r * hn);
    hnew[(size_t)row * cF + f] = (1.f - z) * n + z * hp;
}

__global__ void __launch_bounds__(256) init_h_k(const float* __restrict__ cand, float* __restrict__ h) {
    const size_t idx = (size_t)blockIdx.x * 256 + threadIdx.x;
    const int row = (int)(idx / cF), f = (int)(idx % cF);
    h[idx] = cand[(size_t)row * cD + f];
}
__global__ void __launch_bounds__(256) out_slots_k(
    const float* __restrict__ cand, const float* __restrict__ h, float* __restrict__ out) {
    const size_t idx = (size_t)blockIdx.x * 256 + threadIdx.x;
    const int row = (int)(idx / cD), c = (int)(idx % cD);
    out[idx] = (c < cF) ? h[(size_t)row * cF + c] : cand[idx];
}
__global__ void __launch_bounds__(256) out_attn_k(const float* __restrict__ attn, float* __restrict__ out) {
    const size_t idx = (size_t)blockIdx.x * 256 + threadIdx.x;
    out[(size_t)BSr * cD + idx] = attn[idx];
}

extern "C" void kernel_launch(void* const* d_in, const int* in_sizes, int n_in,
                              void* d_out, int out_size)
{
    const float* cand = (const float*)d_in[0];
    const float* pano = (const float*)d_in[1];
    const void* mask = d_in[2];
    const float* Wq = (const float*)d_in[3];
    const float* bq = (const float*)d_in[4];
    const float* Wk = (const float*)d_in[5];
    const float* bk = (const float*)d_in[6];
    const float* Wv = (const float*)d_in[7];
    const float* bv = (const float*)d_in[8];
    const float* W_ih = (const float*)d_in[9];
    const float* b_ih = (const float*)d_in[10];
    const float* W_hh = (const float*)d_in[11];
    const float* b_hh = (const float*)d_in[12];
    const float* W1 = (const float*)d_in[13];
    const float* b1 = (const float*)d_in[14];
    const float* W2 = (const float*)d_in[15];
    const float* b2 = (const float*)d_in[16];
    const float* ln_in_g = (const float*)d_in[17];
    const float* ln_in_b = (const float*)d_in[18];
    const float* ln_slots_g = (const float*)d_in[19];
    const float* ln_slots_b = (const float*)d_in[20];
    const float* ln_pre_g = (const float*)d_in[21];
    const float* ln_pre_b = (const float*)d_in[22];
    float* out = (float*)d_out;

    float *p_k, *p_v, *p_q, *p_gi, *p_gh, *p_h, *p_hnew, *p_attn;
    __nv_bfloat16 *b_pano, *b_s, *b_upd, *b_h, *b_pre, *b_hid;
    __nv_bfloat16 *b_wq, *b_wk, *b_wv, *b_wih, *b_whh, *b_w1, *b_w2;
    cudaGetSymbolAddress((void**)&p_k, g_k);
    cudaGetSymbolAddress((void**)&p_v, g_v);
    cudaGetSymbolAddress((void**)&p_q, g_q);
    cudaGetSymbolAddress((void**)&p_gi, g_gi);
    cudaGetSymbolAddress((void**)&p_gh, g_gh);
    cudaGetSymbolAddress((void**)&p_h, g_h);
    cudaGetSymbolAddress((void**)&p_hnew, g_hnew);
    cudaGetSymbolAddress((void**)&p_attn, g_attn);
    cudaGetSymbolAddress((void**)&b_pano, g_pano_b);
    cudaGetSymbolAddress((void**)&b_s, g_s_b);
    cudaGetSymbolAddress((void**)&b_upd, g_upd_b);
    cudaGetSymbolAddress((void**)&b_h, g_h_b);
    cudaGetSymbolAddress((void**)&b_pre, g_pre_b);
    cudaGetSymbolAddress((void**)&b_hid, g_hid_b);
    cudaGetSymbolAddress((void**)&b_wq, g_wq_b);
    cudaGetSymbolAddress((void**)&b_wk, g_wk_b);
    cudaGetSymbolAddress((void**)&b_wv, g_wv_b);
    cudaGetSymbolAddress((void**)&b_wih, g_wih_b);
    cudaGetSymbolAddress((void**)&b_whh, g_whh_b);
    cudaGetSymbolAddress((void**)&b_w1, g_w1_b);
    cudaGetSymbolAddress((void**)&b_w2, g_w2_b);

    cudaFuncSetAttribute(gemm_mma<false, false, 0>, cudaFuncAttributeMaxDynamicSharedMemorySize, SMB);
    cudaFuncSetAttribute(gemm_mma<true, false, 1>, cudaFuncAttributeMaxDynamicSharedMemorySize, SMB);
    cudaFuncSetAttribute(gemm_mma<false, true, 2>, cudaFuncAttributeMaxDynamicSharedMemorySize, SMB);

    detect_mask_k<<<1, 256>>>((const unsigned char*)mask);

    // weight conversions ([hi|lo|hi] blocks)
    conv_w_k<<<(2176 * 1088) / 256, 256>>>(Wq, b_wq, 2176, K1D);
    conv_w_k<<<(2176 * 1088) / 256, 256>>>(Wk, b_wk, 2176, K1D);
    conv_w_k<<<(2176 * 1088) / 256, 256>>>(Wv, b_wv, 2176, K1D);
    conv_w_k<<<(6144 * 1088) / 256, 256>>>(W_ih, b_wih, 2176, K1D);
    conv_w_k<<<(6144 * 1024) / 256, 256>>>(W_hh, b_whh, 2048, K1F);
    conv_w_k<<<(2176 * 1024) / 256, 256>>>(W1, b_w1, 2048, K1F);
    conv_w_k<<<(2048 * 1088) / 256, 256>>>(W2, b_w2, 2176, K1D);

    ln_bf16_k<true><<<BNr, 256>>>(pano, cD, pano, ln_in_g, ln_in_b, b_pano, 2176, K1D);
    gemm_mma<false, false, 0><<<dim3(17, 288), 256, SMB>>>(b_pano, b_wk, bk, nullptr, p_k, KTD, 2176, nullptr, 0);
    gemm_mma<false, false, 0><<<dim3(17, 288), 256, SMB>>>(b_pano, b_wv, bv, nullptr, p_v, KTD, 2176, nullptr, 0);

    init_h_k<<<(BSr * cF) / 256, 256>>>(cand, p_h);
    conv_act_k<<<(BSr * 1024) / 256, 256>>>(p_h, cF, b_h, 2048, K1F);

    for (int it = 0; it < 3; it++) {
        ln_bf16_k<true><<<BSr, 256>>>(p_h, cF, cand, ln_slots_g, ln_slots_b, b_s, 2176, K1D);
        gemm_mma<false, false, 0><<<dim3(17, 80), 256, SMB>>>(b_s, b_wq, bq, nullptr, p_q, KTD, 2176, nullptr, 0);
        attn_k<<<cB, 256>>>(mask, p_q, p_k, p_v, p_attn, b_upd);
        gemm_mma<false, false, 0><<<dim3(48, 80), 256, SMB>>>(b_upd, b_wih, b_ih, nullptr, p_gi, KTD, 6144, nullptr, 0);
        gemm_mma<false, false, 0><<<dim3(48, 80), 256, SMB>>>(b_h, b_whh, b_hh, nullptr, p_gh, KTF, 6144, nullptr, 0);
        gru_k<<<(BSr * cF) / 256, 256>>>(p_gi, p_gh, p_h, p_hnew);
        ln_bf16_k<false><<<BSr, 256>>>(p_hnew, cF, nullptr, ln_pre_g, ln_pre_b, b_pre, 2048, K1F);
        gemm_mma<true, false, 1><<<dim3(17, 80), 256, SMB>>>(b_pre, b_w1, b1, nullptr, nullptr, KTF, 2176, b_hid, K1D);
        gemm_mma<false, true, 2><<<dim3(16, 80), 256, SMB>>>(b_hid, b_w2, b2, p_hnew, p_h, KTD, 2048, b_h, K1F);
    }

    out_slots_k<<<(BSr * cD) / 256, 256>>>(cand, p_h, out);
    out_attn_k<<<(BSr * cN) / 256, 256>>>(p_attn, out);
}

// round 8
// speedup vs baseline: 1.1688x; 1.0414x over previous
#include <cuda_runtime.h>
#include <cuda_bf16.h>
#include <math.h>
#include <stdint.h>

constexpr int cB = 1024, cS = 10, cN = 36, cF = 2048, cD = 2176;
constexpr int BSr = cB * cS, BNr = cB * cN, G3 = 3 * cF;
constexpr int K3D = 3 * cD, K3F = 3 * cF;        // 6528 / 6144
constexpr int KTD = K3D / 64, KTF = K3F / 64;    // 102 / 96 (total K' tiles)
constexpr int K1D = cD / 64, K1F = cF / 64;      // 34 / 32 (base k-tiles)

// fp32 scratch
__device__ float g_k[(size_t)BNr * cD];
__device__ float g_v[(size_t)BNr * cD];
__device__ float g_q[(size_t)BSr * cD];
__device__ float g_gi[(size_t)BSr * G3];
__device__ float g_gh[(size_t)BSr * G3];
__device__ float g_h[(size_t)BSr * cF];
__device__ float g_hnew[(size_t)BSr * cF];
__device__ float g_attn[(size_t)BSr * cN];
__device__ int g_mask_mode;

// bf16 split operands ([hi|hi|lo] for A, [hi|lo|hi] for W), pre-swizzled
// 128x64 16KB tile blocks.
__device__ __align__(256) __nv_bfloat16 g_pano_b[(size_t)BNr * K3D];
__device__ __align__(256) __nv_bfloat16 g_s_b [(size_t)BSr * K3D];
__device__ __align__(256) __nv_bfloat16 g_upd_b[(size_t)BSr * K3D];
__device__ __align__(256) __nv_bfloat16 g_h_b [(size_t)BSr * K3F];
__device__ __align__(256) __nv_bfloat16 g_pre_b[(size_t)BSr * K3F];
__device__ __align__(256) __nv_bfloat16 g_hid_b[(size_t)BSr * K3D];
__device__ __align__(256) __nv_bfloat16 g_wq_b [(size_t)2176 * K3D];
__device__ __align__(256) __nv_bfloat16 g_wk_b [(size_t)2176 * K3D];
__device__ __align__(256) __nv_bfloat16 g_wv_b [(size_t)2176 * K3D];
__device__ __align__(256) __nv_bfloat16 g_wih_b[(size_t)6144 * K3D];
__device__ __align__(256) __nv_bfloat16 g_whh_b[(size_t)6144 * K3F];
__device__ __align__(256) __nv_bfloat16 g_w1_b [(size_t)2176 * K3F];
__device__ __align__(256) __nv_bfloat16 g_w2_b [(size_t)2048 * K3D];

__device__ __forceinline__ uint32_t smem_u32(const void* p) {
    uint32_t a;
    asm("{ .reg .u64 t; cvta.to.shared.u64 t, %1; cvt.u32.u64 %0, t; }" : "=r"(a) : "l"(p));
    return a;
}
#define MBAR_INIT(a, c) asm volatile("mbarrier.init.shared.b64 [%0], %1;" :: "r"(a), "r"(c) : "memory")
#define MBAR_EXPECT_TX(a, b) asm volatile("mbarrier.arrive.expect_tx.shared.b64 _, [%0], %1;" :: "r"(a), "r"(b) : "memory")
#define MBAR_ARRIVE(a) asm volatile("mbarrier.arrive.shared.b64 _, [%0];" :: "r"(a) : "memory")
#define MBAR_WAIT(a, p) do { \
    uint32_t _m = (a), _p = (p), _d; \
    asm volatile("{\n\t.reg .pred q;\n\tmbarrier.try_wait.parity.acquire.cta.shared::cta.b64 q, [%1], %2;\n\tselp.b32 %0, 1, 0, q;\n\t}" \
        : "=r"(_d) : "r"(_m), "r"(_p) : "memory"); \
    if (!_d) { \
        asm volatile("{\n\t.reg .pred P1;\n\tWL_%=:\n\tmbarrier.try_wait.parity.acquire.cta.shared::cta.b64 P1, [%0], %1, 0x989680;\n\t@P1 bra.uni WD_%=;\n\tbra.uni WL_%=;\n\tWD_%=:\n\t}" \
            :: "r"(_m), "r"(_p) : "memory"); \
    } } while (0)

__device__ __forceinline__ void bulk_g2s(uint32_t dst, const void* src, uint32_t bytes, uint32_t mbar) {
    asm volatile("cp.async.bulk.shared::cluster.global.mbarrier::complete_tx::bytes [%0], [%1], %2, [%3];"
        :: "r"(dst), "l"(src), "r"(bytes), "r"(mbar) : "memory");
}

__device__ __forceinline__ uint32_t packbf(float a, float b) {
    return (uint32_t)__bfloat16_as_ushort(__float2bfloat16_rn(a)) |
           ((uint32_t)__bfloat16_as_ushort(__float2bfloat16_rn(b)) << 16);
}
__device__ __forceinline__ float residf(float a) {
    return a - __bfloat162float(__float2bfloat16_rn(a));
}
__device__ __forceinline__ uint32_t swz(uint32_t o) { return o ^ ((o >> 3) & 0x70); }

// A-side split write: hi at block t, hi at t+kt1, lo at t+2*kt1 (kt1 = Kx/64)
__device__ __forceinline__ void put3a(char* base, int rb, int kt1, int r, int col,
                                      uint32_t hi, uint32_t lo) {
    const int t = col >> 6, cc = col & 63;
    const uint32_t so = swz(((uint32_t)r << 7) + ((uint32_t)cc << 1));
    char* p = base + (((size_t)rb * 3 * kt1 + t) << 14) + so;
    *(uint32_t*)p = hi;
    *(uint32_t*)(p + ((size_t)kt1 << 14)) = hi;
    *(uint32_t*)(p + ((size_t)(2 * kt1) << 14)) = lo;
}
// W-side split write: hi at t, lo at t+kt1, hi at t+2*kt1
__device__ __forceinline__ void put3w(char* base, int rb, int kt1, int r, int col,
                                      uint32_t hi, uint32_t lo) {
    const int t = col >> 6, cc = col & 63;
    const uint32_t so = swz(((uint32_t)r << 7) + ((uint32_t)cc << 1));
    char* p = base + (((size_t)rb * 3 * kt1 + t) << 14) + so;
    *(uint32_t*)p = hi;
    *(uint32_t*)(p + ((size_t)kt1 << 14)) = lo;
    *(uint32_t*)(p + ((size_t)(2 * kt1) << 14)) = hi;
}

__global__ void detect_mask_k(const unsigned char* __restrict__ m) {
    __shared__ int c1, c3f;
    if (threadIdx.x == 0) { c1 = 0; c3f = 0; }
    __syncthreads();
    int l1 = 0, l3 = 0;
    for (int i = threadIdx.x; i < BSr; i += 256) {
        unsigned char v = m[i];
        if ((i & 3) != 0 && v == 1) l1++;
        if (v == 0x3f) l3++;
    }
    atomicAdd(&c1, l1); atomicAdd(&c3f, l3);
    __syncthreads();
    if (threadIdx.x == 0) g_mask_mode = (c3f > 0) ? 2 : (c1 > 0 ? 0 : 1);
}

// LN over cF cols of x (stride xs); cols [cF,Kx) from tailsrc (stride cD).
template <bool TAIL>
__global__ void __launch_bounds__(256) ln_bf16_k(
    const float* __restrict__ x, int xs, const float* __restrict__ tailsrc,
    const float* __restrict__ gam, const float* __restrict__ bet,
    __nv_bfloat16* __restrict__ dst, int Kx, int kt1)
{
    const int row = blockIdx.x, tid = threadIdx.x;
    const float* xr = x + (size_t)row * xs;
    float s = 0.f, s2 = 0.f;
    for (int c = tid * 4; c < cF; c += 1024) {
        float4 v = *reinterpret_cast<const float4*>(xr + c);
        s += v.x + v.y + v.z + v.w;
        s2 += v.x * v.x + v.y * v.y + v.z * v.z + v.w * v.w;
    }
    #pragma unroll
    for (int o = 16; o; o >>= 1) {
        s += __shfl_xor_sync(0xffffffffu, s, o);
        s2 += __shfl_xor_sync(0xffffffffu, s2, o);
    }
    __shared__ float ws[8], ws2[8];
    const int warp = tid >> 5, lane = tid & 31;
    if (lane == 0) { ws[warp] = s; ws2[warp] = s2; }
    __syncthreads();
    if (tid == 0) {
        float a = 0.f, b2 = 0.f;
        #pragma unroll
        for (int w = 0; w < 8; w++) { a += ws[w]; b2 += ws2[w]; }
        ws[0] = a; ws2[0] = b2;
    }
    __syncthreads();
    const float mean = ws[0] * (1.f / cF);
    const float rstd = rsqrtf(ws2[0] * (1.f / cF) - mean * mean + 1e-5f);
    const int mt = row >> 7, r = row & 127;
    char* db = (char*)dst;
    for (int p = tid; p < (Kx >> 1); p += 256) {
        const int c = 2 * p;
        float a, b;
        if (c < cF) {
            a = (xr[c] - mean) * rstd * gam[c] + bet[c];
            b = (xr[c + 1] - mean) * rstd * gam[c + 1] + bet[c + 1];
        } else {
            a = TAIL ? tailsrc[(size_t)row * cD + c] : 0.f;
            b = TAIL ? tailsrc[(size_t)row * cD + c + 1] : 0.f;
        }
        put3a(db, mt, kt1, r, c, packbf(a, b), packbf(residf(a), residf(b)));
    }
}

__global__ void __launch_bounds__(256) conv_act_k(
    const float* __restrict__ x, int xs, __nv_bfloat16* __restrict__ dst, int Kx, int kt1)
{
    const int Kh = Kx >> 1;
    const size_t idx = (size_t)blockIdx.x * 256 + threadIdx.x;
    const int row = (int)(idx / Kh), c = 2 * (int)(idx % Kh);
    const float a = x[(size_t)row * xs + c], b = x[(size_t)row * xs + c + 1];
    put3a((char*)dst, row >> 7, kt1, row & 127, c, packbf(a, b), packbf(residf(a), residf(b)));
}

__global__ void __launch_bounds__(256) conv_w_k(
    const float* __restrict__ w, __nv_bfloat16* __restrict__ dst, int Kx, int kt1)
{
    const int Kh = Kx >> 1;
    const size_t idx = (size_t)blockIdx.x * 256 + threadIdx.x;
    const int row = (int)(idx / Kh), c = 2 * (int)(idx % Kh);
    const float a = w[(size_t)row * Kx + c], b = w[(size_t)row * Kx + c + 1];
    put3w((char*)dst, row >> 7, kt1, row & 127, c, packbf(a, b), packbf(residf(a), residf(b)));
}

// mma.sync GEMM core: C[M,Nc] = A'[M,K'] @ W'[Nc,K']^T; BM=BN=128 BK=64,
// 8 warps (4x2), warp tile 32x64, 3-stage bulk pipeline with full/empty
// mbarriers (no per-tile __syncthreads), 2 CTA/SM.
// SPLIT: 0 = fp32 C only; 1 = split blocks only; 2 = fp32 C + split blocks.
constexpr int STG = 32768, SD0 = 1024, SMB = SD0 + 3 * STG;

template <bool RELU, bool ADD, int SPLIT>
__device__ __forceinline__ void gemm_core(
    const __nv_bfloat16* __restrict__ Ab, const __nv_bfloat16* __restrict__ Wb,
    const float* __restrict__ bias, const float* __restrict__ addsrc,
    float* __restrict__ C, int ktiles, int Nc,
    __nv_bfloat16* __restrict__ sdst, int skt1, int nt, int mt)
{
    extern __shared__ __align__(1024) char smem[];
    const uint32_t sb = smem_u32(smem);
    const int tid = threadIdx.x, warp = tid >> 5, lane = tid & 31;

    // full[s] = sb + 8s (count 1, tx); empty[s] = sb + 24 + 8s (count 256)
    if (tid == 0) {
        #pragma unroll
        for (int s = 0; s < 3; s++) { MBAR_INIT(sb + 8 * s, 1); MBAR_INIT(sb + 24 + 8 * s, 256); }
    }
    __syncthreads();

    const char* Ag = (const char*)Ab + (size_t)mt * ktiles * 16384;
    const char* Wg = (const char*)Wb + (size_t)nt * ktiles * 16384;

    if (tid == 0) {
        #pragma unroll
        for (int s = 0; s < 3; s++) {
            MBAR_EXPECT_TX(sb + 8 * s, 32768);
            bulk_g2s(sb + SD0 + s * STG, Ag + (size_t)s * 16384, 16384, sb + 8 * s);
            bulk_g2s(sb + SD0 + s * STG + 16384, Wg + (size_t)s * 16384, 16384, sb + 8 * s);
        }
    }

    const int m0w = (warp >> 1) << 5;
    const int n0w = (warp & 1) << 6;
    const int arow = m0w + (lane & 15);
    const uint32_t aoff0 = (uint32_t)arow << 7;
    const uint32_t axor = (uint32_t)(arow & 7) << 4;
    const uint32_t akh = (uint32_t)(lane >> 4) << 4;
    const uint32_t boff0 = (uint32_t)(n0w + lane) << 7;
    const uint32_t bxor = (uint32_t)(lane & 7) << 4;

    float acc[2][8][4];
    #pragma unroll
    for (int i = 0; i < 2; i++)
        #pragma unroll
        for (int j = 0; j < 8; j++)
            #pragma unroll
            for (int q = 0; q < 4; q++) acc[i][j][q] = 0.f;

    int s = 0, ph = 0;
    #pragma unroll 1
    for (int kt = 0; kt < ktiles; kt++) {
        MBAR_WAIT(sb + 8 * s, ph);
        const uint32_t As = sb + SD0 + s * STG;
        const uint32_t Bs = As + 16384;
        #pragma unroll
        for (int kk = 0; kk < 4; kk++) {
            uint32_t a[2][4];
            const uint32_t kbA = ((kk << 5) | akh) ^ axor;
            #pragma unroll
            for (int im = 0; im < 2; im++) {
                uint32_t ad = As + aoff0 + (im << 11) + kbA;
                asm volatile("ldmatrix.sync.aligned.m8n8.x4.shared.b16 {%0,%1,%2,%3}, [%4];"
                    : "=r"(a[im][0]), "=r"(a[im][1]), "=r"(a[im][2]), "=r"(a[im][3]) : "r"(ad));
            }
            uint32_t b0[8], b1[8];
            #pragma unroll
            for (int q = 0; q < 2; q++) {
                uint32_t bd = Bs + boff0 + (q << 12);
                uint32_t k0 = (kk << 5) ^ bxor;
                uint32_t k1 = ((kk << 5) | 16) ^ bxor;
                asm volatile("ldmatrix.sync.aligned.m8n8.x4.shared.b16 {%0,%1,%2,%3}, [%4];"
                    : "=r"(b0[q*4+0]), "=r"(b0[q*4+1]), "=r"(b0[q*4+2]), "=r"(b0[q*4+3]) : "r"(bd + k0));
                asm volatile("ldmatrix.sync.aligned.m8n8.x4.shared.b16 {%0,%1,%2,%3}, [%4];"
                    : "=r"(b1[q*4+0]), "=r"(b1[q*4+1]), "=r"(b1[q*4+2]), "=r"(b1[q*4+3]) : "r"(bd + k1));
            }
            #pragma unroll
            for (int im = 0; im < 2; im++)
                #pragma unroll
                for (int ng = 0; ng < 8; ng++)
                    asm volatile("mma.sync.aligned.m16n8k16.row.col.f32.bf16.bf16.f32 "
                        "{%0,%1,%2,%3}, {%4,%5,%6,%7}, {%8,%9}, {%0,%1,%2,%3};"
                        : "+f"(acc[im][ng][0]), "+f"(acc[im][ng][1]),
                          "+f"(acc[im][ng][2]), "+f"(acc[im][ng][3])
                        : "r"(a[im][0]), "r"(a[im][1]), "r"(a[im][2]), "r"(a[im][3]),
                          "r"(b0[ng]), "r"(b1[ng]));
        }
        MBAR_ARRIVE(sb + 24 + 8 * s);
        if (tid == 0 && kt + 3 < ktiles) {
            MBAR_WAIT(sb + 24 + 8 * s, ph);   // all 256 done reading stage s
            MBAR_EXPECT_TX(sb + 8 * s, 32768);
            bulk_g2s(sb + SD0 + s * STG, Ag + (size_t)(kt + 3) * 16384, 16384, sb + 8 * s);
            bulk_g2s(sb + SD0 + s * STG + 16384, Wg + (size_t)(kt + 3) * 16384, 16384, sb + 8 * s);
        }
        if (++s == 3) { s = 0; ph ^= 1; }
    }

    const int rb = mt * 128 + m0w + (lane >> 2);
    const int cb = nt * 128 + n0w + ((lane & 3) << 1);
    #pragma unroll
    for (int im = 0; im < 2; im++) {
        #pragma unroll
        for (int ng = 0; ng < 8; ng++) {
            const int r0 = rb + im * 16, c = cb + ng * 8;
            const float bx = bias[c], by = bias[c + 1];
            float2 v0 = make_float2(acc[im][ng][0] + bx, acc[im][ng][1] + by);
            float2 v1 = make_float2(acc[im][ng][2] + bx, acc[im][ng][3] + by);
            if (RELU) {
                v0.x = fmaxf(v0.x, 0.f); v0.y = fmaxf(v0.y, 0.f);
                v1.x = fmaxf(v1.x, 0.f); v1.y = fmaxf(v1.y, 0.f);
            }
            if (ADD) {
                const float2 a0 = *(const float2*)(addsrc + (size_t)r0 * Nc + c);
                const float2 a1 = *(const float2*)(addsrc + (size_t)(r0 + 8) * Nc + c);
                v0.x += a0.x; v0.y += a0.y; v1.x += a1.x; v1.y += a1.y;
            }
            if (SPLIT != 1) {
                *(float2*)(C + (size_t)r0 * Nc + c) = v0;
                *(float2*)(C + (size_t)(r0 + 8) * Nc + c) = v1;
            }
            if (SPLIT != 0) {
                put3a((char*)sdst, r0 >> 7, skt1, r0 & 127, c,
                      packbf(v0.x, v0.y), packbf(residf(v0.x), residf(v0.y)));
                put3a((char*)sdst, (r0 + 8) >> 7, skt1, (r0 + 8) & 127, c,
                      packbf(v1.x, v1.y), packbf(residf(v1.x), residf(v1.y)));
            }
        }
    }
}

template <bool RELU, bool ADD, int SPLIT>
__global__ void __launch_bounds__(256, 2) gemm_mma(
    const __nv_bfloat16* __restrict__ Ab, const __nv_bfloat16* __restrict__ Wb,
    const float* __restrict__ bias, const float* __restrict__ addsrc,
    float* __restrict__ C, int ktiles, int Nc,
    __nv_bfloat16* __restrict__ sdst, int skt1)
{
    gemm_core<RELU, ADD, SPLIT>(Ab, Wb, bias, addsrc, C, ktiles, Nc, sdst, skt1,
                                blockIdx.x, blockIdx.y);
}

struct GemmP {
    const __nv_bfloat16* A;
    const __nv_bfloat16* W;
    const float* bias;
    float* C;
    int ktiles;
};

__global__ void __launch_bounds__(256, 2) gemm_dual(GemmP p0, GemmP p1, int Nc) {
    const GemmP p = blockIdx.z ? p1 : p0;
    gemm_core<false, false, 0>(p.A, p.W, p.bias, nullptr, p.C, p.ktiles, Nc,
                               nullptr, 0, blockIdx.x, blockIdx.y);
}

// attention: dots -> masked softmax(axis=i) -> attn @ v, writes split upd blocks
__global__ void __launch_bounds__(256) attn_k(
    const void* __restrict__ mask, const float* __restrict__ q,
    const float* __restrict__ kk, const float* __restrict__ vv,
    float* __restrict__ attn_out, __nv_bfloat16* __restrict__ upd_b)
{
    const int b = blockIdx.x;
    __shared__ float sd[cS][cN];
    __shared__ float smask[cS];
    const int tid = threadIdx.x;
    if (tid < cS) {
        const int mm = g_mask_mode;
        const int idx = b * cS + tid;
        bool mk;
        if (mm == 0)      mk = ((const unsigned char*)mask)[idx] != 0;
        else if (mm == 1) mk = ((const int*)mask)[idx] != 0;
        else              mk = ((const float*)mask)[idx] != 0.f;
        smask[tid] = mk ? 1.f : 0.f;
    }
    __syncthreads();
    const int warp = tid >> 5, lane = tid & 31;
    const float scale = rsqrtf((float)cD);
    for (int p = warp; p < cS * cN; p += 8) {
        const int i = p / cN, j = p % cN;
        const float* qr = q + (size_t)(b * cS + i) * cD;
        const float* kr = kk + (size_t)(b * cN + j) * cD;
        float sum = 0.f;
        for (int d = lane * 4; d < cD; d += 128) {
            float4 qa = *reinterpret_cast<const float4*>(qr + d);
            float4 ka = *reinterpret_cast<const float4*>(kr + d);
            sum += qa.x * ka.x + qa.y * ka.y + qa.z * ka.z + qa.w * ka.w;
        }
        #pragma unroll
        for (int o = 16; o; o >>= 1) sum += __shfl_xor_sync(0xffffffffu, sum, o);
        if (lane == 0) sd[i][j] = (smask[i] > 0.f) ? -INFINITY : sum * scale;
    }
    __syncthreads();
    if (tid < cN) {
        const int j = tid;
        float m = -INFINITY;
        #pragma unroll
        for (int i = 0; i < cS; i++) m = fmaxf(m, sd[i][j]);
        float e[cS], ssum = 0.f;
        #pragma unroll
        for (int i = 0; i < cS; i++) { e[i] = expf(sd[i][j] - m); ssum += e[i]; }
        const float inv = 1.f / ssum;
        #pragma unroll
        for (int i = 0; i < cS; i++) {
            const float a = e[i] * inv;
            sd[i][j] = a;
            attn_out[(size_t)(b * cS + i) * cN + j] = a;
        }
    }
    __syncthreads();
    for (int d = tid * 2; d < cD; d += 512) {
        float a0[cS], a1[cS];
        #pragma unroll
        for (int i = 0; i < cS; i++) { a0[i] = 0.f; a1[i] = 0.f; }
        for (int j = 0; j < cN; j++) {
            const float2 vj = *(const float2*)(vv + (size_t)(b * cN + j) * cD + d);
            #pragma unroll
            for (int i = 0; i < cS; i++) {
                a0[i] = fmaf(sd[i][j], vj.x, a0[i]);
                a1[i] = fmaf(sd[i][j], vj.y, a1[i]);
            }
        }
        #pragma unroll
        for (int i = 0; i < cS; i++) {
            const int row = b * cS + i;
            put3a((char*)upd_b, row >> 7, K1D, row & 127, d,
                  packbf(a0[i], a1[i]), packbf(residf(a0[i]), residf(a1[i])));
        }
    }
}

__global__ void __launch_bounds__(256) gru_k(
    const float* __restrict__ gi, const float* __restrict__ gh,
    const float* __restrict__ h, float* __restrict__ hnew)
{
    const size_t idx = (size_t)blockIdx.x * 256 + threadIdx.x;
    const int row = (int)(idx / cF), f = (int)(idx % cF);
    const size_t o = (size_t)row * G3 + f;
    const float ir = gi[o], iz = gi[o + cF], inn = gi[o + 2 * cF];
    const float hr = gh[o], hz = gh[o + cF], hn = gh[o + 2 * cF];
    const float hp = h[(size_t)row * cF + f];
    const float r = 1.f / (1.f + expf(-(ir + hr)));
    const float z = 1.f / (1.f + expf(-(iz + hz)));
    const float n = tanhf(inn + r * hn);
    hnew[(size_t)row * cF + f] = (1.f - z) * n + z * hp;
}

__global__ void __launch_bounds__(256) init_h_k(const float* __restrict__ cand, float* __restrict__ h) {
    const size_t idx = (size_t)blockIdx.x * 256 + threadIdx.x;
    const int row = (int)(idx / cF), f = (int)(idx % cF);
    h[idx] = cand[(size_t)row * cD + f];
}
__global__ void __launch_bounds__(256) out_slots_k(
    const float* __restrict__ cand, const float* __restrict__ h, float* __restrict__ out) {
    const size_t idx = (size_t)blockIdx.x * 256 + threadIdx.x;
    const int row = (int)(idx / cD), c = (int)(idx % cD);
    out[idx] = (c < cF) ? h[(size_t)row * cF + c] : cand[idx];
}
__global__ void __launch_bounds__(256) out_attn_k(const float* __restrict__ attn, float* __restrict__ out) {
    const size_t idx = (size_t)blockIdx.x * 256 + threadIdx.x;
    out[(size_t)BSr * cD + idx] = attn[idx];
}

extern "C" void kernel_launch(void* const* d_in, const int* in_sizes, int n_in,
                              void* d_out, int out_size)
{
    const float* cand = (const float*)d_in[0];
    const float* pano = (const float*)d_in[1];
    const void* mask = d_in[2];
    const float* Wq = (const float*)d_in[3];
    const float* bq = (const float*)d_in[4];
    const float* Wk = (const float*)d_in[5];
    const float* bk = (const float*)d_in[6];
    const float* Wv = (const float*)d_in[7];
    const float* bv = (const float*)d_in[8];
    const float* W_ih = (const float*)d_in[9];
    const float* b_ih = (const float*)d_in[10];
    const float* W_hh = (const float*)d_in[11];
    const float* b_hh = (const float*)d_in[12];
    const float* W1 = (const float*)d_in[13];
    const float* b1 = (const float*)d_in[14];
    const float* W2 = (const float*)d_in[15];
    const float* b2 = (const float*)d_in[16];
    const float* ln_in_g = (const float*)d_in[17];
    const float* ln_in_b = (const float*)d_in[18];
    const float* ln_slots_g = (const float*)d_in[19];
    const float* ln_slots_b = (const float*)d_in[20];
    const float* ln_pre_g = (const float*)d_in[21];
    const float* ln_pre_b = (const float*)d_in[22];
    float* out = (float*)d_out;

    float *p_k, *p_v, *p_q, *p_gi, *p_gh, *p_h, *p_hnew, *p_attn;
    __nv_bfloat16 *b_pano, *b_s, *b_upd, *b_h, *b_pre, *b_hid;
    __nv_bfloat16 *b_wq, *b_wk, *b_wv, *b_wih, *b_whh, *b_w1, *b_w2;
    cudaGetSymbolAddress((void**)&p_k, g_k);
    cudaGetSymbolAddress((void**)&p_v, g_v);
    cudaGetSymbolAddress((void**)&p_q, g_q);
    cudaGetSymbolAddress((void**)&p_gi, g_gi);
    cudaGetSymbolAddress((void**)&p_gh, g_gh);
    cudaGetSymbolAddress((void**)&p_h, g_h);
    cudaGetSymbolAddress((void**)&p_hnew, g_hnew);
    cudaGetSymbolAddress((void**)&p_attn, g_attn);
    cudaGetSymbolAddress((void**)&b_pano, g_pano_b);
    cudaGetSymbolAddress((void**)&b_s, g_s_b);
    cudaGetSymbolAddress((void**)&b_upd, g_upd_b);
    cudaGetSymbolAddress((void**)&b_h, g_h_b);
    cudaGetSymbolAddress((void**)&b_pre, g_pre_b);
    cudaGetSymbolAddress((void**)&b_hid, g_hid_b);
    cudaGetSymbolAddress((void**)&b_wq, g_wq_b);
    cudaGetSymbolAddress((void**)&b_wk, g_wk_b);
    cudaGetSymbolAddress((void**)&b_wv, g_wv_b);
    cudaGetSymbolAddress((void**)&b_wih, g_wih_b);
    cudaGetSymbolAddress((void**)&b_whh, g_whh_b);
    cudaGetSymbolAddress((void**)&b_w1, g_w1_b);
    cudaGetSymbolAddress((void**)&b_w2, g_w2_b);

    cudaFuncSetAttribute(gemm_mma<false, false, 0>, cudaFuncAttributeMaxDynamicSharedMemorySize, SMB);
    cudaFuncSetAttribute(gemm_mma<true, false, 1>, cudaFuncAttributeMaxDynamicSharedMemorySize, SMB);
    cudaFuncSetAttribute(gemm_mma<false, true, 2>, cudaFuncAttributeMaxDynamicSharedMemorySize, SMB);
    cudaFuncSetAttribute(gemm_dual, cudaFuncAttributeMaxDynamicSharedMemorySize, SMB);

    detect_mask_k<<<1, 256>>>((const unsigned char*)mask);

    // weight conversions ([hi|lo|hi] blocks)
    conv_w_k<<<(2176 * 1088) / 256, 256>>>(Wq, b_wq, 2176, K1D);
    conv_w_k<<<(2176 * 1088) / 256, 256>>>(Wk, b_wk, 2176, K1D);
    conv_w_k<<<(2176 * 1088) / 256, 256>>>(Wv, b_wv, 2176, K1D);
    conv_w_k<<<(6144 * 1088) / 256, 256>>>(W_ih, b_wih, 2176, K1D);
    conv_w_k<<<(6144 * 1024) / 256, 256>>>(W_hh, b_whh, 2048, K1F);
    conv_w_k<<<(2176 * 1024) / 256, 256>>>(W1, b_w1, 2048, K1F);
    conv_w_k<<<(2048 * 1088) / 256, 256>>>(W2, b_w2, 2176, K1D);

    ln_bf16_k<true><<<BNr, 256>>>(pano, cD, pano, ln_in_g, ln_in_b, b_pano, 2176, K1D);
    {
        GemmP pk = { b_pano, b_wk, bk, p_k, KTD };
        GemmP pv = { b_pano, b_wv, bv, p_v, KTD };
        gemm_dual<<<dim3(17, 288, 2), 256, SMB>>>(pk, pv, 2176);
    }

    init_h_k<<<(BSr * cF) / 256, 256>>>(cand, p_h);
    conv_act_k<<<(BSr * 1024) / 256, 256>>>(p_h, cF, b_h, 2048, K1F);

    for (int it = 0; it < 3; it++) {
        ln_bf16_k<true><<<BSr, 256>>>(p_h, cF, cand, ln_slots_g, ln_slots_b, b_s, 2176, K1D);
        gemm_mma<false, false, 0><<<dim3(17, 80), 256, SMB>>>(b_s, b_wq, bq, nullptr, p_q, KTD, 2176, nullptr, 0);
        attn_k<<<cB, 256>>>(mask, p_q, p_k, p_v, p_attn, b_upd);
        {
            GemmP pi = { b_upd, b_wih, b_ih, p_gi, KTD };
            GemmP ph = { b_h,   b_whh, b_hh, p_gh, KTF };
            gemm_dual<<<dim3(48, 80, 2), 256, SMB>>>(pi, ph, 6144);
        }
        gru_k<<<(BSr * cF) / 256, 256>>>(p_gi, p_gh, p_h, p_hnew);
        ln_bf16_k<false><<<BSr, 256>>>(p_hnew, cF, nullptr, ln_pre_g, ln_pre_b, b_pre, 2048, K1F);
        gemm_mma<true, false, 1><<<dim3(17, 80), 256, SMB>>>(b_pre, b_w1, b1, nullptr, nullptr, KTF, 2176, b_hid, K1D);
        gemm_mma<false, true, 2><<<dim3(16, 80), 256, SMB>>>(b_hid, b_w2, b2, p_hnew, p_h, KTD, 2048, b_h, K1F);
    }

    out_slots_k<<<(BSr * cD) / 256, 256>>>(cand, p_h, out);
    out_attn_k<<<(BSr * cN) / 256, 256>>>(p_attn, out);
}

// round 9
// speedup vs baseline: 1.6601x; 1.4203x over previous
#include <cuda_runtime.h>
#include <cuda_bf16.h>
#include <cuda_fp16.h>
#include <math.h>
#include <stdint.h>

constexpr int cB = 1024, cS = 10, cN = 36, cF = 2048, cD = 2176;
constexpr int BSr = cB * cS, BNr = cB * cN, G3 = 3 * cF;
constexpr int K3D = 3 * cD, K3F = 3 * cF;        // 6528 / 6144
constexpr int KTD = K3D / 64, KTF = K3F / 64;    // 102 / 96 (total K' tiles, bf16 path)
constexpr int K1D = cD / 64, K1F = cF / 64;      // 34 / 32 (base k-tiles)

// fp32 scratch
__device__ float g_k[(size_t)BNr * cD];
__device__ float g_v[(size_t)BNr * cD];
__device__ float g_q[(size_t)BSr * cD];
__device__ float g_gi[(size_t)BSr * G3];
__device__ float g_gh[(size_t)BSr * G3];
__device__ float g_h[(size_t)BSr * cF];
__device__ float g_hnew[(size_t)BSr * cF];
__device__ float g_attn[(size_t)BSr * cN];
__device__ int g_mask_mode;

// bf16 split operands ([hi|hi|lo] for A, [hi|lo|hi] for W), pre-swizzled
// 128x64 16KB tile blocks — used by k/v/q/W1/W2 GEMMs.
__device__ __align__(256) __nv_bfloat16 g_pano_b[(size_t)BNr * K3D];
__device__ __align__(256) __nv_bfloat16 g_s_b [(size_t)BSr * K3D];
__device__ __align__(256) __nv_bfloat16 g_pre_b[(size_t)BSr * K3F];
__device__ __align__(256) __nv_bfloat16 g_hid_b[(size_t)BSr * K3D];
__device__ __align__(256) __nv_bfloat16 g_wq_b [(size_t)2176 * K3D];
__device__ __align__(256) __nv_bfloat16 g_wk_b [(size_t)2176 * K3D];
__device__ __align__(256) __nv_bfloat16 g_wv_b [(size_t)2176 * K3D];
__device__ __align__(256) __nv_bfloat16 g_w1_b [(size_t)2176 * K3F];
__device__ __align__(256) __nv_bfloat16 g_w2_b [(size_t)2048 * K3D];

// fp16 single-panel operands (1-pass path: gi, gh GEMMs)
__device__ __align__(256) __half g_upd_h[(size_t)BSr * cD];
__device__ __align__(256) __half g_h_h [(size_t)BSr * cF];
__device__ __align__(256) __half g_wih_h[(size_t)6144 * cD];
__device__ __align__(256) __half g_whh_h[(size_t)6144 * cF];

__device__ __forceinline__ uint32_t smem_u32(const void* p) {
    uint32_t a;
    asm("{ .reg .u64 t; cvta.to.shared.u64 t, %1; cvt.u32.u64 %0, t; }" : "=r"(a) : "l"(p));
    return a;
}
#define MBAR_INIT(a, c) asm volatile("mbarrier.init.shared.b64 [%0], %1;" :: "r"(a), "r"(c) : "memory")
#define MBAR_EXPECT_TX(a, b) asm volatile("mbarrier.arrive.expect_tx.shared.b64 _, [%0], %1;" :: "r"(a), "r"(b) : "memory")
#define MBAR_ARRIVE(a) asm volatile("mbarrier.arrive.shared.b64 _, [%0];" :: "r"(a) : "memory")
#define MBAR_WAIT(a, p) do { \
    uint32_t _m = (a), _p = (p), _d; \
    asm volatile("{\n\t.reg .pred q;\n\tmbarrier.try_wait.parity.acquire.cta.shared::cta.b64 q, [%1], %2;\n\tselp.b32 %0, 1, 0, q;\n\t}" \
        : "=r"(_d) : "r"(_m), "r"(_p) : "memory"); \
    if (!_d) { \
        asm volatile("{\n\t.reg .pred P1;\n\tWL_%=:\n\tmbarrier.try_wait.parity.acquire.cta.shared::cta.b64 P1, [%0], %1, 0x989680;\n\t@P1 bra.uni WD_%=;\n\tbra.uni WL_%=;\n\tWD_%=:\n\t}" \
            :: "r"(_m), "r"(_p) : "memory"); \
    } } while (0)

__device__ __forceinline__ void bulk_g2s(uint32_t dst, const void* src, uint32_t bytes, uint32_t mbar) {
    asm volatile("cp.async.bulk.shared::cluster.global.mbarrier::complete_tx::bytes [%0], [%1], %2, [%3];"
        :: "r"(dst), "l"(src), "r"(bytes), "r"(mbar) : "memory");
}

__device__ __forceinline__ uint32_t packbf(float a, float b) {
    return (uint32_t)__bfloat16_as_ushort(__float2bfloat16_rn(a)) |
           ((uint32_t)__bfloat16_as_ushort(__float2bfloat16_rn(b)) << 16);
}
__device__ __forceinline__ uint32_t packh(float a, float b) {
    __half2 h = __floats2half2_rn(a, b);
    return *reinterpret_cast<uint32_t*>(&h);
}
__device__ __forceinline__ float residf(float a) {
    return a - __bfloat162float(__float2bfloat16_rn(a));
}
__device__ __forceinline__ uint32_t swz(uint32_t o) { return o ^ ((o >> 3) & 0x70); }

// single-panel write (fp16 hi-only path)
__device__ __forceinline__ void put1(char* base, int rb, int kt1, int r, int col, uint32_t v) {
    const int t = col >> 6, cc = col & 63;
    *(uint32_t*)(base + (((size_t)rb * kt1 + t) << 14) + swz(((uint32_t)r << 7) + ((uint32_t)cc << 1))) = v;
}
// A-side split write: hi at block t, hi at t+kt1, lo at t+2*kt1
__device__ __forceinline__ void put3a(char* base, int rb, int kt1, int r, int col,
                                      uint32_t hi, uint32_t lo) {
    const int t = col >> 6, cc = col & 63;
    const uint32_t so = swz(((uint32_t)r << 7) + ((uint32_t)cc << 1));
    char* p = base + (((size_t)rb * 3 * kt1 + t) << 14) + so;
    *(uint32_t*)p = hi;
    *(uint32_t*)(p + ((size_t)kt1 << 14)) = hi;
    *(uint32_t*)(p + ((size_t)(2 * kt1) << 14)) = lo;
}
// W-side split write: hi at t, lo at t+kt1, hi at t+2*kt1
__device__ __forceinline__ void put3w(char* base, int rb, int kt1, int r, int col,
                                      uint32_t hi, uint32_t lo) {
    const int t = col >> 6, cc = col & 63;
    const uint32_t so = swz(((uint32_t)r << 7) + ((uint32_t)cc << 1));
    char* p = base + (((size_t)rb * 3 * kt1 + t) << 14) + so;
    *(uint32_t*)p = hi;
    *(uint32_t*)(p + ((size_t)kt1 << 14)) = lo;
    *(uint32_t*)(p + ((size_t)(2 * kt1) << 14)) = hi;
}

__global__ void detect_mask_k(const unsigned char* __restrict__ m) {
    __shared__ int c1, c3f;
    if (threadIdx.x == 0) { c1 = 0; c3f = 0; }
    __syncthreads();
    int l1 = 0, l3 = 0;
    for (int i = threadIdx.x; i < BSr; i += 256) {
        unsigned char v = m[i];
        if ((i & 3) != 0 && v == 1) l1++;
        if (v == 0x3f) l3++;
    }
    atomicAdd(&c1, l1); atomicAdd(&c3f, l3);
    __syncthreads();
    if (threadIdx.x == 0) g_mask_mode = (c3f > 0) ? 2 : (c1 > 0 ? 0 : 1);
}

// LN over cF cols of x (stride xs); cols [cF,Kx) from tailsrc (stride cD).
template <bool TAIL>
__global__ void __launch_bounds__(256) ln_bf16_k(
    const float* __restrict__ x, int xs, const float* __restrict__ tailsrc,
    const float* __restrict__ gam, const float* __restrict__ bet,
    __nv_bfloat16* __restrict__ dst, int Kx, int kt1)
{
    const int row = blockIdx.x, tid = threadIdx.x;
    const float* xr = x + (size_t)row * xs;
    float s = 0.f, s2 = 0.f;
    for (int c = tid * 4; c < cF; c += 1024) {
        float4 v = *reinterpret_cast<const float4*>(xr + c);
        s += v.x + v.y + v.z + v.w;
        s2 += v.x * v.x + v.y * v.y + v.z * v.z + v.w * v.w;
    }
    #pragma unroll
    for (int o = 16; o; o >>= 1) {
        s += __shfl_xor_sync(0xffffffffu, s, o);
        s2 += __shfl_xor_sync(0xffffffffu, s2, o);
    }
    __shared__ float ws[8], ws2[8];
    const int warp = tid >> 5, lane = tid & 31;
    if (lane == 0) { ws[warp] = s; ws2[warp] = s2; }
    __syncthreads();
    if (tid == 0) {
        float a = 0.f, b2 = 0.f;
        #pragma unroll
        for (int w = 0; w < 8; w++) { a += ws[w]; b2 += ws2[w]; }
        ws[0] = a; ws2[0] = b2;
    }
    __syncthreads();
    const float mean = ws[0] * (1.f / cF);
    const float rstd = rsqrtf(ws2[0] * (1.f / cF) - mean * mean + 1e-5f);
    const int mt = row >> 7, r = row & 127;
    char* db = (char*)dst;
    for (int p = tid; p < (Kx >> 1); p += 256) {
        const int c = 2 * p;
        float a, b;
        if (c < cF) {
            a = (xr[c] - mean) * rstd * gam[c] + bet[c];
            b = (xr[c + 1] - mean) * rstd * gam[c + 1] + bet[c + 1];
        } else {
            a = TAIL ? tailsrc[(size_t)row * cD + c] : 0.f;
            b = TAIL ? tailsrc[(size_t)row * cD + c + 1] : 0.f;
        }
        put3a(db, mt, kt1, r, c, packbf(a, b), packbf(residf(a), residf(b)));
    }
}

// fp16 single-panel conversions
__global__ void __launch_bounds__(256) conv_act_h_k(
    const float* __restrict__ x, int xs, __half* __restrict__ dst, int Kx, int kt1)
{
    const int Kh = Kx >> 1;
    const size_t idx = (size_t)blockIdx.x * 256 + threadIdx.x;
    const int row = (int)(idx / Kh), c = 2 * (int)(idx % Kh);
    put1((char*)dst, row >> 7, kt1, row & 127, c,
         packh(x[(size_t)row * xs + c], x[(size_t)row * xs + c + 1]));
}

__global__ void __launch_bounds__(256) conv_w_h_k(
    const float* __restrict__ w, __half* __restrict__ dst, int Kx, int kt1)
{
    const int Kh = Kx >> 1;
    const size_t idx = (size_t)blockIdx.x * 256 + threadIdx.x;
    const int row = (int)(idx / Kh), c = 2 * (int)(idx % Kh);
    put1((char*)dst, row >> 7, kt1, row & 127, c,
         packh(w[(size_t)row * Kx + c], w[(size_t)row * Kx + c + 1]));
}

__global__ void __launch_bounds__(256) conv_w_k(
    const float* __restrict__ w, __nv_bfloat16* __restrict__ dst, int Kx, int kt1)
{
    const int Kh = Kx >> 1;
    const size_t idx = (size_t)blockIdx.x * 256 + threadIdx.x;
    const int row = (int)(idx / Kh), c = 2 * (int)(idx % Kh);
    const float a = w[(size_t)row * Kx + c], b = w[(size_t)row * Kx + c + 1];
    put3w((char*)dst, row >> 7, kt1, row & 127, c, packbf(a, b), packbf(residf(a), residf(b)));
}

// DT: 0 = bf16 mma, 1 = fp16 mma
template <int DT>
__device__ __forceinline__ void mma16816(float* c, const uint32_t* a, uint32_t b0, uint32_t b1) {
    if (DT == 0)
        asm volatile("mma.sync.aligned.m16n8k16.row.col.f32.bf16.bf16.f32 "
            "{%0,%1,%2,%3}, {%4,%5,%6,%7}, {%8,%9}, {%0,%1,%2,%3};"
            : "+f"(c[0]), "+f"(c[1]), "+f"(c[2]), "+f"(c[3])
            : "r"(a[0]), "r"(a[1]), "r"(a[2]), "r"(a[3]), "r"(b0), "r"(b1));
    else
        asm volatile("mma.sync.aligned.m16n8k16.row.col.f32.f16.f16.f32 "
            "{%0,%1,%2,%3}, {%4,%5,%6,%7}, {%8,%9}, {%0,%1,%2,%3};"
            : "+f"(c[0]), "+f"(c[1]), "+f"(c[2]), "+f"(c[3])
            : "r"(a[0]), "r"(a[1]), "r"(a[2]), "r"(a[3]), "r"(b0), "r"(b1));
}

// mma.sync GEMM core: C[M,Nc] = A[M,K] @ W[Nc,K]^T; BM=BN=128 BK=64,
// 8 warps (4x2), warp tile 32x64, 3-stage bulk pipeline w/ full+empty mbarriers.
// SPLIT: 0 = fp32 C only; 1 = bf16 3-panel only; 2 = fp32 C + fp16 1-panel.
constexpr int STG = 32768, SD0 = 1024, SMB = SD0 + 3 * STG;

template <bool RELU, bool ADD, int SPLIT, int DT>
__device__ __forceinline__ void gemm_core(
    const void* __restrict__ Ab, const void* __restrict__ Wb,
    const float* __restrict__ bias, const float* __restrict__ addsrc,
    float* __restrict__ C, int ktiles, int Nc,
    void* __restrict__ sdst, int skt1, int nt, int mt)
{
    extern __shared__ __align__(1024) char smem[];
    const uint32_t sb = smem_u32(smem);
    const int tid = threadIdx.x, warp = tid >> 5, lane = tid & 31;

    if (tid == 0) {
        #pragma unroll
        for (int s = 0; s < 3; s++) { MBAR_INIT(sb + 8 * s, 1); MBAR_INIT(sb + 24 + 8 * s, 256); }
    }
    __syncthreads();

    const char* Ag = (const char*)Ab + (size_t)mt * ktiles * 16384;
    const char* Wg = (const char*)Wb + (size_t)nt * ktiles * 16384;

    if (tid == 0) {
        #pragma unroll
        for (int s = 0; s < 3; s++) {
            MBAR_EXPECT_TX(sb + 8 * s, 32768);
            bulk_g2s(sb + SD0 + s * STG, Ag + (size_t)s * 16384, 16384, sb + 8 * s);
            bulk_g2s(sb + SD0 + s * STG + 16384, Wg + (size_t)s * 16384, 16384, sb + 8 * s);
        }
    }

    const int m0w = (warp >> 1) << 5;
    const int n0w = (warp & 1) << 6;
    const int arow = m0w + (lane & 15);
    const uint32_t aoff0 = (uint32_t)arow << 7;
    const uint32_t axor = (uint32_t)(arow & 7) << 4;
    const uint32_t akh = (uint32_t)(lane >> 4) << 4;
    const uint32_t boff0 = (uint32_t)(n0w + lane) << 7;
    const uint32_t bxor = (uint32_t)(lane & 7) << 4;

    float acc[2][8][4];
    #pragma unroll
    for (int i = 0; i < 2; i++)
        #pragma unroll
        for (int j = 0; j < 8; j++)
            #pragma unroll
            for (int q = 0; q < 4; q++) acc[i][j][q] = 0.f;

    int s = 0, ph = 0;
    #pragma unroll 1
    for (int kt = 0; kt < ktiles; kt++) {
        MBAR_WAIT(sb + 8 * s, ph);
        const uint32_t As = sb + SD0 + s * STG;
        const uint32_t Bs = As + 16384;
        #pragma unroll
        for (int kk = 0; kk < 4; kk++) {
            uint32_t a[2][4];
            const uint32_t kbA = ((kk << 5) | akh) ^ axor;
            #pragma unroll
            for (int im = 0; im < 2; im++) {
                uint32_t ad = As + aoff0 + (im << 11) + kbA;
                asm volatile("ldmatrix.sync.aligned.m8n8.x4.shared.b16 {%0,%1,%2,%3}, [%4];"
                    : "=r"(a[im][0]), "=r"(a[im][1]), "=r"(a[im][2]), "=r"(a[im][3]) : "r"(ad));
            }
            uint32_t b0[8], b1[8];
            #pragma unroll
            for (int q = 0; q < 2; q++) {
                uint32_t bd = Bs + boff0 + (q << 12);
                uint32_t k0 = (kk << 5) ^ bxor;
                uint32_t k1 = ((kk << 5) | 16) ^ bxor;
                asm volatile("ldmatrix.sync.aligned.m8n8.x4.shared.b16 {%0,%1,%2,%3}, [%4];"
                    : "=r"(b0[q*4+0]), "=r"(b0[q*4+1]), "=r"(b0[q*4+2]), "=r"(b0[q*4+3]) : "r"(bd + k0));
                asm volatile("ldmatrix.sync.aligned.m8n8.x4.shared.b16 {%0,%1,%2,%3}, [%4];"
                    : "=r"(b1[q*4+0]), "=r"(b1[q*4+1]), "=r"(b1[q*4+2]), "=r"(b1[q*4+3]) : "r"(bd + k1));
            }
            #pragma unroll
            for (int im = 0; im < 2; im++)
                #pragma unroll
                for (int ng = 0; ng < 8; ng++)
                    mma16816<DT>(acc[im][ng], a[im], b0[ng], b1[ng]);
        }
        MBAR_ARRIVE(sb + 24 + 8 * s);
        if (tid == 0 && kt + 3 < ktiles) {
            MBAR_WAIT(sb + 24 + 8 * s, ph);
            MBAR_EXPECT_TX(sb + 8 * s, 32768);
            bulk_g2s(sb + SD0 + s * STG, Ag + (size_t)(kt + 3) * 16384, 16384, sb + 8 * s);
            bulk_g2s(sb + SD0 + s * STG + 16384, Wg + (size_t)(kt + 3) * 16384, 16384, sb + 8 * s);
        }
        if (++s == 3) { s = 0; ph ^= 1; }
    }

    const int rb = mt * 128 + m0w + (lane >> 2);
    const int cb = nt * 128 + n0w + ((lane & 3) << 1);
    #pragma unroll
    for (int im = 0; im < 2; im++) {
        #pragma unroll
        for (int ng = 0; ng < 8; ng++) {
            const int r0 = rb + im * 16, c = cb + ng * 8;
            const float bx = bias[c], by = bias[c + 1];
            float2 v0 = make_float2(acc[im][ng][0] + bx, acc[im][ng][1] + by);
            float2 v1 = make_float2(acc[im][ng][2] + bx, acc[im][ng][3] + by);
            if (RELU) {
                v0.x = fmaxf(v0.x, 0.f); v0.y = fmaxf(v0.y, 0.f);
                v1.x = fmaxf(v1.x, 0.f); v1.y = fmaxf(v1.y, 0.f);
            }
            if (ADD) {
                const float2 a0 = *(const float2*)(addsrc + (size_t)r0 * Nc + c);
                const float2 a1 = *(const float2*)(addsrc + (size_t)(r0 + 8) * Nc + c);
                v0.x += a0.x; v0.y += a0.y; v1.x += a1.x; v1.y += a1.y;
            }
            if (SPLIT != 1) {
                *(float2*)(C + (size_t)r0 * Nc + c) = v0;
                *(float2*)(C + (size_t)(r0 + 8) * Nc + c) = v1;
            }
            if (SPLIT == 1) {
                put3a((char*)sdst, r0 >> 7, skt1, r0 & 127, c,
                      packbf(v0.x, v0.y), packbf(residf(v0.x), residf(v0.y)));
                put3a((char*)sdst, (r0 + 8) >> 7, skt1, (r0 + 8) & 127, c,
                      packbf(v1.x, v1.y), packbf(residf(v1.x), residf(v1.y)));
            }
            if (SPLIT == 2) {
                put1((char*)sdst, r0 >> 7, skt1, r0 & 127, c, packh(v0.x, v0.y));
                put1((char*)sdst, (r0 + 8) >> 7, skt1, (r0 + 8) & 127, c, packh(v1.x, v1.y));
            }
        }
    }
}

template <bool RELU, bool ADD, int SPLIT, int DT>
__global__ void __launch_bounds__(256, 2) gemm_mma(
    const void* __restrict__ Ab, const void* __restrict__ Wb,
    const float* __restrict__ bias, const float* __restrict__ addsrc,
    float* __restrict__ C, int ktiles, int Nc,
    void* __restrict__ sdst, int skt1)
{
    gemm_core<RELU, ADD, SPLIT, DT>(Ab, Wb, bias, addsrc, C, ktiles, Nc, sdst, skt1,
                                    blockIdx.x, blockIdx.y);
}

struct GemmP {
    const void* A;
    const void* W;
    const float* bias;
    float* C;
    int ktiles;
};

template <int DT>
__global__ void __launch_bounds__(256, 2) gemm_dual(GemmP p0, GemmP p1, int Nc) {
    const GemmP p = blockIdx.z ? p1 : p0;
    gemm_core<false, false, 0, DT>(p.A, p.W, p.bias, nullptr, p.C, p.ktiles, Nc,
                                   nullptr, 0, blockIdx.x, blockIdx.y);
}

// attention: dots -> masked softmax(axis=i) -> attn @ v; writes fp16 upd panel
__global__ void __launch_bounds__(256) attn_k(
    const void* __restrict__ mask, const float* __restrict__ q,
    const float* __restrict__ kk, const float* __restrict__ vv,
    float* __restrict__ attn_out, __half* __restrict__ upd_h)
{
    const int b = blockIdx.x;
    __shared__ float sd[cS][cN];
    __shared__ float smask[cS];
    const int tid = threadIdx.x;
    if (tid < cS) {
        const int mm = g_mask_mode;
        const int idx = b * cS + tid;
        bool mk;
        if (mm == 0)      mk = ((const unsigned char*)mask)[idx] != 0;
        else if (mm == 1) mk = ((const int*)mask)[idx] != 0;
        else              mk = ((const float*)mask)[idx] != 0.f;
        smask[tid] = mk ? 1.f : 0.f;
    }
    __syncthreads();
    const int warp = tid >> 5, lane = tid & 31;
    const float scale = rsqrtf((float)cD);
    for (int p = warp; p < cS * cN; p += 8) {
        const int i = p / cN, j = p % cN;
        const float* qr = q + (size_t)(b * cS + i) * cD;
        const float* kr = kk + (size_t)(b * cN + j) * cD;
        float sum = 0.f;
        for (int d = lane * 4; d < cD; d += 128) {
            float4 qa = *reinterpret_cast<const float4*>(qr + d);
            float4 ka = *reinterpret_cast<const float4*>(kr + d);
            sum += qa.x * ka.x + qa.y * ka.y + qa.z * ka.z + qa.w * ka.w;
        }
        #pragma unroll
        for (int o = 16; o; o >>= 1) sum += __shfl_xor_sync(0xffffffffu, sum, o);
        if (lane == 0) sd[i][j] = (smask[i] > 0.f) ? -INFINITY : sum * scale;
    }
    __syncthreads();
    if (tid < cN) {
        const int j = tid;
        float m = -INFINITY;
        #pragma unroll
        for (int i = 0; i < cS; i++) m = fmaxf(m, sd[i][j]);
        float e[cS], ssum = 0.f;
        #pragma unroll
        for (int i = 0; i < cS; i++) { e[i] = expf(sd[i][j] - m); ssum += e[i]; }
        const float inv = 1.f / ssum;
        #pragma unroll
        for (int i = 0; i < cS; i++) {
            const float a = e[i] * inv;
            sd[i][j] = a;
            attn_out[(size_t)(b * cS + i) * cN + j] = a;
        }
    }
    __syncthreads();
    for (int d = tid * 2; d < cD; d += 512) {
        float a0[cS], a1[cS];
        #pragma unroll
        for (int i = 0; i < cS; i++) { a0[i] = 0.f; a1[i] = 0.f; }
        for (int j = 0; j < cN; j++) {
            const float2 vj = *(const float2*)(vv + (size_t)(b * cN + j) * cD + d);
            #pragma unroll
            for (int i = 0; i < cS; i++) {
                a0[i] = fmaf(sd[i][j], vj.x, a0[i]);
                a1[i] = fmaf(sd[i][j], vj.y, a1[i]);
            }
        }
        #pragma unroll
        for (int i = 0; i < cS; i++) {
            const int row = b * cS + i;
            put1((char*)upd_h, row >> 7, K1D, row & 127, d, packh(a0[i], a1[i]));
        }
    }
}

__global__ void __launch_bounds__(256) gru_k(
    const float* __restrict__ gi, const float* __restrict__ gh,
    const float* __restrict__ h, float* __restrict__ hnew)
{
    const size_t idx = (size_t)blockIdx.x * 256 + threadIdx.x;
    const int row = (int)(idx / cF), f = (int)(idx % cF);
    const size_t o = (size_t)row * G3 + f;
    const float ir = gi[o], iz = gi[o + cF], inn = gi[o + 2 * cF];
    const float hr = gh[o], hz = gh[o + cF], hn = gh[o + 2 * cF];
    const float hp = h[(size_t)row * cF + f];
    const float r = 1.f / (1.f + expf(-(ir + hr)));
    const float z = 1.f / (1.f + expf(-(iz + hz)));
    const float n = tanhf(inn + r * hn);
    hnew[(size_t)row * cF + f] = (1.f - z) * n + z * hp;
}

__global__ void __launch_bounds__(256) init_h_k(const float* __restrict__ cand, float* __restrict__ h) {
    const size_t idx = (size_t)blockIdx.x * 256 + threadIdx.x;
    const int row = (int)(idx / cF), f = (int)(idx % cF);
    h[idx] = cand[(size_t)row * cD + f];
}
__global__ void __launch_bounds__(256) out_slots_k(
    const float* __restrict__ cand, const float* __restrict__ h, float* __restrict__ out) {
    const size_t idx = (size_t)blockIdx.x * 256 + threadIdx.x;
    const int row = (int)(idx / cD), c = (int)(idx % cD);
    out[idx] = (c < cF) ? h[(size_t)row * cF + c] : cand[idx];
}
__global__ void __launch_bounds__(256) out_attn_k(const float* __restrict__ attn, float* __restrict__ out) {
    const size_t idx = (size_t)blockIdx.x * 256 + threadIdx.x;
    out[(size_t)BSr * cD + idx] = attn[idx];
}

extern "C" void kernel_launch(void* const* d_in, const int* in_sizes, int n_in,
                              void* d_out, int out_size)
{
    const float* cand = (const float*)d_in[0];
    const float* pano = (const float*)d_in[1];
    const void* mask = d_in[2];
    const float* Wq = (const float*)d_in[3];
    const float* bq = (const float*)d_in[4];
    const float* Wk = (const float*)d_in[5];
    const float* bk = (const float*)d_in[6];
    const float* Wv = (const float*)d_in[7];
    const float* bv = (const float*)d_in[8];
    const float* W_ih = (const float*)d_in[9];
    const float* b_ih = (const float*)d_in[10];
    const float* W_hh = (const float*)d_in[11];
    const float* b_hh = (const float*)d_in[12];
    const float* W1 = (const float*)d_in[13];
    const float* b1 = (const float*)d_in[14];
    const float* W2 = (const float*)d_in[15];
    const float* b2 = (const float*)d_in[16];
    const float* ln_in_g = (const float*)d_in[17];
    const float* ln_in_b = (const float*)d_in[18];
    const float* ln_slots_g = (const float*)d_in[19];
    const float* ln_slots_b = (const float*)d_in[20];
    const float* ln_pre_g = (const float*)d_in[21];
    const float* ln_pre_b = (const float*)d_in[22];
    float* out = (float*)d_out;

    float *p_k, *p_v, *p_q, *p_gi, *p_gh, *p_h, *p_hnew, *p_attn;
    __nv_bfloat16 *b_pano, *b_s, *b_pre, *b_hid, *b_wq, *b_wk, *b_wv, *b_w1, *b_w2;
    __half *h_upd, *h_h, *h_wih, *h_whh;
    cudaGetSymbolAddress((void**)&p_k, g_k);
    cudaGetSymbolAddress((void**)&p_v, g_v);
    cudaGetSymbolAddress((void**)&p_q, g_q);
    cudaGetSymbolAddress((void**)&p_gi, g_gi);
    cudaGetSymbolAddress((void**)&p_gh, g_gh);
    cudaGetSymbolAddress((void**)&p_h, g_h);
    cudaGetSymbolAddress((void**)&p_hnew, g_hnew);
    cudaGetSymbolAddress((void**)&p_attn, g_attn);
    cudaGetSymbolAddress((void**)&b_pano, g_pano_b);
    cudaGetSymbolAddress((void**)&b_s, g_s_b);
    cudaGetSymbolAddress((void**)&b_pre, g_pre_b);
    cudaGetSymbolAddress((void**)&b_hid, g_hid_b);
    cudaGetSymbolAddress((void**)&b_wq, g_wq_b);
    cudaGetSymbolAddress((void**)&b_wk, g_wk_b);
    cudaGetSymbolAddress((void**)&b_wv, g_wv_b);
    cudaGetSymbolAddress((void**)&b_w1, g_w1_b);
    cudaGetSymbolAddress((void**)&b_w2, g_w2_b);
    cudaGetSymbolAddress((void**)&h_upd, g_upd_h);
    cudaGetSymbolAddress((void**)&h_h, g_h_h);
    cudaGetSymbolAddress((void**)&h_wih, g_wih_h);
    cudaGetSymbolAddress((void**)&h_whh, g_whh_h);

    cudaFuncSetAttribute(gemm_mma<false, false, 0, 0>, cudaFuncAttributeMaxDynamicSharedMemorySize, SMB);
    cudaFuncSetAttribute(gemm_mma<true, false, 1, 0>, cudaFuncAttributeMaxDynamicSharedMemorySize, SMB);
    cudaFuncSetAttribute(gemm_mma<false, true, 2, 0>, cudaFuncAttributeMaxDynamicSharedMemorySize, SMB);
    cudaFuncSetAttribute(gemm_dual<0>, cudaFuncAttributeMaxDynamicSharedMemorySize, SMB);
    cudaFuncSetAttribute(gemm_dual<1>, cudaFuncAttributeMaxDynamicSharedMemorySize, SMB);

    detect_mask_k<<<1, 256>>>((const unsigned char*)mask);

    // weight conversions
    conv_w_k<<<(2176 * 1088) / 256, 256>>>(Wq, b_wq, 2176, K1D);
    conv_w_k<<<(2176 * 1088) / 256, 256>>>(Wk, b_wk, 2176, K1D);
    conv_w_k<<<(2176 * 1088) / 256, 256>>>(Wv, b_wv, 2176, K1D);
    conv_w_h_k<<<(6144 * 1088) / 256, 256>>>(W_ih, h_wih, 2176, K1D);
    conv_w_h_k<<<(6144 * 1024) / 256, 256>>>(W_hh, h_whh, 2048, K1F);
    conv_w_k<<<(2176 * 1024) / 256, 256>>>(W1, b_w1, 2048, K1F);
    conv_w_k<<<(2048 * 1088) / 256, 256>>>(W2, b_w2, 2176, K1D);

    ln_bf16_k<true><<<BNr, 256>>>(pano, cD, pano, ln_in_g, ln_in_b, b_pano, 2176, K1D);
    {
        GemmP pk = { b_pano, b_wk, bk, p_k, KTD };
        GemmP pv = { b_pano, b_wv, bv, p_v, KTD };
        gemm_dual<0><<<dim3(17, 288, 2), 256, SMB>>>(pk, pv, 2176);
    }

    init_h_k<<<(BSr * cF) / 256, 256>>>(cand, p_h);
    conv_act_h_k<<<(BSr * 1024) / 256, 256>>>(p_h, cF, h_h, 2048, K1F);

    for (int it = 0; it < 3; it++) {
        ln_bf16_k<true><<<BSr, 256>>>(p_h, cF, cand, ln_slots_g, ln_slots_b, b_s, 2176, K1D);
        gemm_mma<false, false, 0, 0><<<dim3(17, 80), 256, SMB>>>(b_s, b_wq, bq, nullptr, p_q, KTD, 2176, nullptr, 0);
        attn_k<<<cB, 256>>>(mask, p_q, p_k, p_v, p_attn, h_upd);
        {
            GemmP pi = { h_upd, h_wih, b_ih, p_gi, K1D };
            GemmP ph = { h_h,   h_whh, b_hh, p_gh, K1F };
            gemm_dual<1><<<dim3(48, 80, 2), 256, SMB>>>(pi, ph, 6144);
        }
        gru_k<<<(BSr * cF) / 256, 256>>>(p_gi, p_gh, p_h, p_hnew);
        ln_bf16_k<false><<<BSr, 256>>>(p_hnew, cF, nullptr, ln_pre_g, ln_pre_b, b_pre, 2048, K1F);
        gemm_mma<true, false, 1, 0><<<dim3(17, 80), 256, SMB>>>(b_pre, b_w1, b1, nullptr, nullptr, KTF, 2176, b_hid, K1D);
        gemm_mma<false, true, 2, 0><<<dim3(16, 80), 256, SMB>>>(b_hid, b_w2, b2, p_hnew, p_h, KTD, 2048, h_h, K1F);
    }

    out_slots_k<<<(BSr * cD) / 256, 256>>>(cand, p_h, out);
    out_attn_k<<<(BSr * cN) / 256, 256>>>(p_attn, out);
}

// round 10
// speedup vs baseline: 2.1982x; 1.3241x over previous
#include <cuda_runtime.h>
#include <cuda_bf16.h>
#include <cuda_fp16.h>
#include <math.h>
#include <stdint.h>

constexpr int cB = 1024, cS = 10, cN = 36, cF = 2048, cD = 2176;
constexpr int BSr = cB * cS, BNr = cB * cN, G3 = 3 * cF;
constexpr int K3D = 3 * cD;                      // 6528
constexpr int KTD = K3D / 64;                    // 102 (k/q bf16 3-pass tiles)
constexpr int K1D = cD / 64, K1F = cF / 64;      // 34 / 32 (base k-tiles)

// fp32 scratch
__device__ float g_k[(size_t)BNr * cD];
__device__ float g_v[(size_t)BNr * cD];
__device__ float g_q[(size_t)BSr * cD];
__device__ float g_gi[(size_t)BSr * G3];
__device__ float g_gh[(size_t)BSr * G3];
__device__ float g_h[(size_t)BSr * cF];
__device__ float g_hnew[(size_t)BSr * cF];
__device__ float g_attn[(size_t)BSr * cN];
__device__ int g_mask_mode;

// bf16 split operands ([hi|hi|lo] for A, [hi|lo|hi] for W) — k and q GEMMs
__device__ __align__(256) __nv_bfloat16 g_pano_b[(size_t)BNr * K3D];
__device__ __align__(256) __nv_bfloat16 g_s_b [(size_t)BSr * K3D];
__device__ __align__(256) __nv_bfloat16 g_wq_b [(size_t)2176 * K3D];
__device__ __align__(256) __nv_bfloat16 g_wk_b [(size_t)2176 * K3D];

// fp16 single-panel operands (1-pass GEMMs: v, gi, gh, W1, W2)
__device__ __align__(256) __half g_pano_h[(size_t)BNr * cD];
__device__ __align__(256) __half g_upd_h[(size_t)BSr * cD];
__device__ __align__(256) __half g_h_h [(size_t)BSr * cF];
__device__ __align__(256) __half g_pre_h[(size_t)BSr * cF];
__device__ __align__(256) __half g_hid_h[(size_t)BSr * cD];
__device__ __align__(256) __half g_wv_h [(size_t)2176 * cD];
__device__ __align__(256) __half g_wih_h[(size_t)6144 * cD];
__device__ __align__(256) __half g_whh_h[(size_t)6144 * cF];
__device__ __align__(256) __half g_w1_h [(size_t)2176 * cF];
__device__ __align__(256) __half g_w2_h [(size_t)2048 * cD];

__device__ __forceinline__ uint32_t smem_u32(const void* p) {
    uint32_t a;
    asm("{ .reg .u64 t; cvta.to.shared.u64 t, %1; cvt.u32.u64 %0, t; }" : "=r"(a) : "l"(p));
    return a;
}
#define MBAR_INIT(a, c) asm volatile("mbarrier.init.shared.b64 [%0], %1;" :: "r"(a), "r"(c) : "memory")
#define MBAR_EXPECT_TX(a, b) asm volatile("mbarrier.arrive.expect_tx.shared.b64 _, [%0], %1;" :: "r"(a), "r"(b) : "memory")
#define MBAR_ARRIVE(a) asm volatile("mbarrier.arrive.shared.b64 _, [%0];" :: "r"(a) : "memory")
#define MBAR_WAIT(a, p) do { \
    uint32_t _m = (a), _p = (p), _d; \
    asm volatile("{\n\t.reg .pred q;\n\tmbarrier.try_wait.parity.acquire.cta.shared::cta.b64 q, [%1], %2;\n\tselp.b32 %0, 1, 0, q;\n\t}" \
        : "=r"(_d) : "r"(_m), "r"(_p) : "memory"); \
    if (!_d) { \
        asm volatile("{\n\t.reg .pred P1;\n\tWL_%=:\n\tmbarrier.try_wait.parity.acquire.cta.shared::cta.b64 P1, [%0], %1, 0x989680;\n\t@P1 bra.uni WD_%=;\n\tbra.uni WL_%=;\n\tWD_%=:\n\t}" \
            :: "r"(_m), "r"(_p) : "memory"); \
    } } while (0)

__device__ __forceinline__ void bulk_g2s(uint32_t dst, const void* src, uint32_t bytes, uint32_t mbar) {
    asm volatile("cp.async.bulk.shared::cluster.global.mbarrier::complete_tx::bytes [%0], [%1], %2, [%3];"
        :: "r"(dst), "l"(src), "r"(bytes), "r"(mbar) : "memory");
}

__device__ __forceinline__ uint32_t packbf(float a, float b) {
    return (uint32_t)__bfloat16_as_ushort(__float2bfloat16_rn(a)) |
           ((uint32_t)__bfloat16_as_ushort(__float2bfloat16_rn(b)) << 16);
}
__device__ __forceinline__ uint32_t packh(float a, float b) {
    __half2 h = __floats2half2_rn(a, b);
    return *reinterpret_cast<uint32_t*>(&h);
}
__device__ __forceinline__ float residf(float a) {
    return a - __bfloat162float(__float2bfloat16_rn(a));
}
__device__ __forceinline__ uint32_t swz(uint32_t o) { return o ^ ((o >> 3) & 0x70); }

// single-panel write (fp16 path)
__device__ __forceinline__ void put1(char* base, int rb, int kt1, int r, int col, uint32_t v) {
    const int t = col >> 6, cc = col & 63;
    *(uint32_t*)(base + (((size_t)rb * kt1 + t) << 14) + swz(((uint32_t)r << 7) + ((uint32_t)cc << 1))) = v;
}
// A-side bf16 split: hi at t, hi at t+kt1, lo at t+2*kt1
__device__ __forceinline__ void put3a(char* base, int rb, int kt1, int r, int col,
                                      uint32_t hi, uint32_t lo) {
    const int t = col >> 6, cc = col & 63;
    const uint32_t so = swz(((uint32_t)r << 7) + ((uint32_t)cc << 1));
    char* p = base + (((size_t)rb * 3 * kt1 + t) << 14) + so;
    *(uint32_t*)p = hi;
    *(uint32_t*)(p + ((size_t)kt1 << 14)) = hi;
    *(uint32_t*)(p + ((size_t)(2 * kt1) << 14)) = lo;
}
// W-side bf16 split: hi at t, lo at t+kt1, hi at t+2*kt1
__device__ __forceinline__ void put3w(char* base, int rb, int kt1, int r, int col,
                                      uint32_t hi, uint32_t lo) {
    const int t = col >> 6, cc = col & 63;
    const uint32_t so = swz(((uint32_t)r << 7) + ((uint32_t)cc << 1));
    char* p = base + (((size_t)rb * 3 * kt1 + t) << 14) + so;
    *(uint32_t*)p = hi;
    *(uint32_t*)(p + ((size_t)kt1 << 14)) = lo;
    *(uint32_t*)(p + ((size_t)(2 * kt1) << 14)) = hi;
}

__global__ void detect_mask_k(const unsigned char* __restrict__ m) {
    __shared__ int c1, c3f;
    if (threadIdx.x == 0) { c1 = 0; c3f = 0; }
    __syncthreads();
    int l1 = 0, l3 = 0;
    for (int i = threadIdx.x; i < BSr; i += 256) {
        unsigned char v = m[i];
        if ((i & 3) != 0 && v == 1) l1++;
        if (v == 0x3f) l3++;
    }
    atomicAdd(&c1, l1); atomicAdd(&c3f, l3);
    __syncthreads();
    if (threadIdx.x == 0) g_mask_mode = (c3f > 0) ? 2 : (c1 > 0 ? 0 : 1);
}

// LN over cF cols of x (stride xs); cols [cF,Kx) from tailsrc (stride cD).
// WBF: write bf16 3-panel to dstB (kt1 blocks); WH: write fp16 1-panel to dstH (kth blocks).
template <bool TAIL, bool WBF, bool WH>
__global__ void __launch_bounds__(256) ln_conv_k(
    const float* __restrict__ x, int xs, const float* __restrict__ tailsrc,
    const float* __restrict__ gam, const float* __restrict__ bet,
    __nv_bfloat16* __restrict__ dstB, int kt1,
    __half* __restrict__ dstH, int kth, int Kx)
{
    const int row = blockIdx.x, tid = threadIdx.x;
    const float* xr = x + (size_t)row * xs;
    float s = 0.f, s2 = 0.f;
    for (int c = tid * 4; c < cF; c += 1024) {
        float4 v = *reinterpret_cast<const float4*>(xr + c);
        s += v.x + v.y + v.z + v.w;
        s2 += v.x * v.x + v.y * v.y + v.z * v.z + v.w * v.w;
    }
    #pragma unroll
    for (int o = 16; o; o >>= 1) {
        s += __shfl_xor_sync(0xffffffffu, s, o);
        s2 += __shfl_xor_sync(0xffffffffu, s2, o);
    }
    __shared__ float ws[8], ws2[8];
    const int warp = tid >> 5, lane = tid & 31;
    if (lane == 0) { ws[warp] = s; ws2[warp] = s2; }
    __syncthreads();
    if (tid == 0) {
        float a = 0.f, b2 = 0.f;
        #pragma unroll
        for (int w = 0; w < 8; w++) { a += ws[w]; b2 += ws2[w]; }
        ws[0] = a; ws2[0] = b2;
    }
    __syncthreads();
    const float mean = ws[0] * (1.f / cF);
    const float rstd = rsqrtf(ws2[0] * (1.f / cF) - mean * mean + 1e-5f);
    const int mt = row >> 7, r = row & 127;
    for (int p = tid; p < (Kx >> 1); p += 256) {
        const int c = 2 * p;
        float a, b;
        if (c < cF) {
            a = (xr[c] - mean) * rstd * gam[c] + bet[c];
            b = (xr[c + 1] - mean) * rstd * gam[c + 1] + bet[c + 1];
        } else {
            a = TAIL ? tailsrc[(size_t)row * cD + c] : 0.f;
            b = TAIL ? tailsrc[(size_t)row * cD + c + 1] : 0.f;
        }
        if (WBF) put3a((char*)dstB, mt, kt1, r, c, packbf(a, b), packbf(residf(a), residf(b)));
        if (WH)  put1((char*)dstH, mt, kth, r, c, packh(a, b));
    }
}

__global__ void __launch_bounds__(256) conv_act_h_k(
    const float* __restrict__ x, int xs, __half* __restrict__ dst, int Kx, int kt1)
{
    const int Kh = Kx >> 1;
    const size_t idx = (size_t)blockIdx.x * 256 + threadIdx.x;
    const int row = (int)(idx / Kh), c = 2 * (int)(idx % Kh);
    put1((char*)dst, row >> 7, kt1, row & 127, c,
         packh(x[(size_t)row * xs + c], x[(size_t)row * xs + c + 1]));
}

__global__ void __launch_bounds__(256) conv_w_h_k(
    const float* __restrict__ w, __half* __restrict__ dst, int Kx, int kt1)
{
    const int Kh = Kx >> 1;
    const size_t idx = (size_t)blockIdx.x * 256 + threadIdx.x;
    const int row = (int)(idx / Kh), c = 2 * (int)(idx % Kh);
    put1((char*)dst, row >> 7, kt1, row & 127, c,
         packh(w[(size_t)row * Kx + c], w[(size_t)row * Kx + c + 1]));
}

__global__ void __launch_bounds__(256) conv_w_k(
    const float* __restrict__ w, __nv_bfloat16* __restrict__ dst, int Kx, int kt1)
{
    const int Kh = Kx >> 1;
    const size_t idx = (size_t)blockIdx.x * 256 + threadIdx.x;
    const int row = (int)(idx / Kh), c = 2 * (int)(idx % Kh);
    const float a = w[(size_t)row * Kx + c], b = w[(size_t)row * Kx + c + 1];
    put3w((char*)dst, row >> 7, kt1, row & 127, c, packbf(a, b), packbf(residf(a), residf(b)));
}

// DT: 0 = bf16 mma, 1 = fp16 mma
template <int DT>
__device__ __forceinline__ void mma16816(float* c, const uint32_t* a, uint32_t b0, uint32_t b1) {
    if (DT == 0)
        asm volatile("mma.sync.aligned.m16n8k16.row.col.f32.bf16.bf16.f32 "
            "{%0,%1,%2,%3}, {%4,%5,%6,%7}, {%8,%9}, {%0,%1,%2,%3};"
            : "+f"(c[0]), "+f"(c[1]), "+f"(c[2]), "+f"(c[3])
            : "r"(a[0]), "r"(a[1]), "r"(a[2]), "r"(a[3]), "r"(b0), "r"(b1));
    else
        asm volatile("mma.sync.aligned.m16n8k16.row.col.f32.f16.f16.f32 "
            "{%0,%1,%2,%3}, {%4,%5,%6,%7}, {%8,%9}, {%0,%1,%2,%3};"
            : "+f"(c[0]), "+f"(c[1]), "+f"(c[2]), "+f"(c[3])
            : "r"(a[0]), "r"(a[1]), "r"(a[2]), "r"(a[3]), "r"(b0), "r"(b1));
}

// mma.sync GEMM core: BM=BN=128 BK=64, 8 warps, 3-stage bulk pipeline.
// SPLIT: 0 = fp32 C only; 2 = fp32 C + fp16 panel; 3 = fp16 panel only.
constexpr int STG = 32768, SD0 = 1024, SMB = SD0 + 3 * STG;

template <bool RELU, bool ADD, int SPLIT, int DT>
__device__ __forceinline__ void gemm_core(
    const void* __restrict__ Ab, const void* __restrict__ Wb,
    const float* __restrict__ bias, const float* __restrict__ addsrc,
    float* __restrict__ C, int ktiles, int Nc,
    void* __restrict__ sdst, int skt1, int nt, int mt)
{
    extern __shared__ __align__(1024) char smem[];
    const uint32_t sb = smem_u32(smem);
    const int tid = threadIdx.x, warp = tid >> 5, lane = tid & 31;

    if (tid == 0) {
        #pragma unroll
        for (int s = 0; s < 3; s++) { MBAR_INIT(sb + 8 * s, 1); MBAR_INIT(sb + 24 + 8 * s, 256); }
    }
    __syncthreads();

    const char* Ag = (const char*)Ab + (size_t)mt * ktiles * 16384;
    const char* Wg = (const char*)Wb + (size_t)nt * ktiles * 16384;

    if (tid == 0) {
        #pragma unroll
        for (int s = 0; s < 3; s++) {
            MBAR_EXPECT_TX(sb + 8 * s, 32768);
            bulk_g2s(sb + SD0 + s * STG, Ag + (size_t)s * 16384, 16384, sb + 8 * s);
            bulk_g2s(sb + SD0 + s * STG + 16384, Wg + (size_t)s * 16384, 16384, sb + 8 * s);
        }
    }

    const int m0w = (warp >> 1) << 5;
    const int n0w = (warp & 1) << 6;
    const int arow = m0w + (lane & 15);
    const uint32_t aoff0 = (uint32_t)arow << 7;
    const uint32_t axor = (uint32_t)(arow & 7) << 4;
    const uint32_t akh = (uint32_t)(lane >> 4) << 4;
    const uint32_t boff0 = (uint32_t)(n0w + lane) << 7;
    const uint32_t bxor = (uint32_t)(lane & 7) << 4;

    float acc[2][8][4];
    #pragma unroll
    for (int i = 0; i < 2; i++)
        #pragma unroll
        for (int j = 0; j < 8; j++)
            #pragma unroll
            for (int q = 0; q < 4; q++) acc[i][j][q] = 0.f;

    int s = 0, ph = 0;
    #pragma unroll 1
    for (int kt = 0; kt < ktiles; kt++) {
        MBAR_WAIT(sb + 8 * s, ph);
        const uint32_t As = sb + SD0 + s * STG;
        const uint32_t Bs = As + 16384;
        #pragma unroll
        for (int kk = 0; kk < 4; kk++) {
            uint32_t a[2][4];
            const uint32_t kbA = ((kk << 5) | akh) ^ axor;
            #pragma unroll
            for (int im = 0; im < 2; im++) {
                uint32_t ad = As + aoff0 + (im << 11) + kbA;
                asm volatile("ldmatrix.sync.aligned.m8n8.x4.shared.b16 {%0,%1,%2,%3}, [%4];"
                    : "=r"(a[im][0]), "=r"(a[im][1]), "=r"(a[im][2]), "=r"(a[im][3]) : "r"(ad));
            }
            uint32_t b0[8], b1[8];
            #pragma unroll
            for (int q = 0; q < 2; q++) {
                uint32_t bd = Bs + boff0 + (q << 12);
                uint32_t k0 = (kk << 5) ^ bxor;
                uint32_t k1 = ((kk << 5) | 16) ^ bxor;
                asm volatile("ldmatrix.sync.aligned.m8n8.x4.shared.b16 {%0,%1,%2,%3}, [%4];"
                    : "=r"(b0[q*4+0]), "=r"(b0[q*4+1]), "=r"(b0[q*4+2]), "=r"(b0[q*4+3]) : "r"(bd + k0));
                asm volatile("ldmatrix.sync.aligned.m8n8.x4.shared.b16 {%0,%1,%2,%3}, [%4];"
                    : "=r"(b1[q*4+0]), "=r"(b1[q*4+1]), "=r"(b1[q*4+2]), "=r"(b1[q*4+3]) : "r"(bd + k1));
            }
            #pragma unroll
            for (int im = 0; im < 2; im++)
                #pragma unroll
                for (int ng = 0; ng < 8; ng++)
                    mma16816<DT>(acc[im][ng], a[im], b0[ng], b1[ng]);
        }
        MBAR_ARRIVE(sb + 24 + 8 * s);
        if (tid == 0 && kt + 3 < ktiles) {
            MBAR_WAIT(sb + 24 + 8 * s, ph);
            MBAR_EXPECT_TX(sb + 8 * s, 32768);
            bulk_g2s(sb + SD0 + s * STG, Ag + (size_t)(kt + 3) * 16384, 16384, sb + 8 * s);
            bulk_g2s(sb + SD0 + s * STG + 16384, Wg + (size_t)(kt + 3) * 16384, 16384, sb + 8 * s);
        }
        if (++s == 3) { s = 0; ph ^= 1; }
    }

    const int rb = mt * 128 + m0w + (lane >> 2);
    const int cb = nt * 128 + n0w + ((lane & 3) << 1);
    #pragma unroll
    for (int im = 0; im < 2; im++) {
        #pragma unroll
        for (int ng = 0; ng < 8; ng++) {
            const int r0 = rb + im * 16, c = cb + ng * 8;
            const float bx = bias[c], by = bias[c + 1];
            float2 v0 = make_float2(acc[im][ng][0] + bx, acc[im][ng][1] + by);
            float2 v1 = make_float2(acc[im][ng][2] + bx, acc[im][ng][3] + by);
            if (RELU) {
                v0.x = fmaxf(v0.x, 0.f); v0.y = fmaxf(v0.y, 0.f);
                v1.x = fmaxf(v1.x, 0.f); v1.y = fmaxf(v1.y, 0.f);
            }
            if (ADD) {
                const float2 a0 = *(const float2*)(addsrc + (size_t)r0 * Nc + c);
                const float2 a1 = *(const float2*)(addsrc + (size_t)(r0 + 8) * Nc + c);
                v0.x += a0.x; v0.y += a0.y; v1.x += a1.x; v1.y += a1.y;
            }
            if (SPLIT != 3) {
                *(float2*)(C + (size_t)r0 * Nc + c) = v0;
                *(float2*)(C + (size_t)(r0 + 8) * Nc + c) = v1;
            }
            if (SPLIT == 2 || SPLIT == 3) {
                put1((char*)sdst, r0 >> 7, skt1, r0 & 127, c, packh(v0.x, v0.y));
                put1((char*)sdst, (r0 + 8) >> 7, skt1, (r0 + 8) & 127, c, packh(v1.x, v1.y));
            }
        }
    }
}

template <bool RELU, bool ADD, int SPLIT, int DT>
__global__ void __launch_bounds__(256, 2) gemm_mma(
    const void* __restrict__ Ab, const void* __restrict__ Wb,
    const float* __restrict__ bias, const float* __restrict__ addsrc,
    float* __restrict__ C, int ktiles, int Nc,
    void* __restrict__ sdst, int skt1)
{
    gemm_core<RELU, ADD, SPLIT, DT>(Ab, Wb, bias, addsrc, C, ktiles, Nc, sdst, skt1,
                                    blockIdx.x, blockIdx.y);
}

struct GemmP {
    const void* A;
    const void* W;
    const float* bias;
    float* C;
    int ktiles;
};

template <int DT0, int DT1>
__global__ void __launch_bounds__(256, 2) gemm_dual(GemmP p0, GemmP p1, int Nc) {
    if (blockIdx.z == 0)
        gemm_core<false, false, 0, DT0>(p0.A, p0.W, p0.bias, nullptr, p0.C, p0.ktiles, Nc,
                                        nullptr, 0, blockIdx.x, blockIdx.y);
    else
        gemm_core<false, false, 0, DT1>(p1.A, p1.W, p1.bias, nullptr, p1.C, p1.ktiles, Nc,
                                        nullptr, 0, blockIdx.x, blockIdx.y);
}

// attention: dots -> masked softmax(axis=i) -> attn @ v; writes fp16 upd panel
__global__ void __launch_bounds__(256) attn_k(
    const void* __restrict__ mask, const float* __restrict__ q,
    const float* __restrict__ kk, const float* __restrict__ vv,
    float* __restrict__ attn_out, __half* __restrict__ upd_h)
{
    const int b = blockIdx.x;
    __shared__ float sd[cS][cN];
    __shared__ float smask[cS];
    const int tid = threadIdx.x;
    if (tid < cS) {
        const int mm = g_mask_mode;
        const int idx = b * cS + tid;
        bool mk;
        if (mm == 0)      mk = ((const unsigned char*)mask)[idx] != 0;
        else if (mm == 1) mk = ((const int*)mask)[idx] != 0;
        else              mk = ((const float*)mask)[idx] != 0.f;
        smask[tid] = mk ? 1.f : 0.f;
    }
    __syncthreads();
    const int warp = tid >> 5, lane = tid & 31;
    const float scale = rsqrtf((float)cD);
    for (int p = warp; p < cS * cN; p += 8) {
        const int i = p / cN, j = p % cN;
        const float* qr = q + (size_t)(b * cS + i) * cD;
        const float* kr = kk + (size_t)(b * cN + j) * cD;
        float sum = 0.f;
        for (int d = lane * 4; d < cD; d += 128) {
            float4 qa = *reinterpret_cast<const float4*>(qr + d);
            float4 ka = *reinterpret_cast<const float4*>(kr + d);
            sum += qa.x * ka.x + qa.y * ka.y + qa.z * ka.z + qa.w * ka.w;
        }
        #pragma unroll
        for (int o = 16; o; o >>= 1) sum += __shfl_xor_sync(0xffffffffu, sum, o);
        if (lane == 0) sd[i][j] = (smask[i] > 0.f) ? -INFINITY : sum * scale;
    }
    __syncthreads();
    if (tid < cN) {
        const int j = tid;
        float m = -INFINITY;
        #pragma unroll
        for (int i = 0; i < cS; i++) m = fmaxf(m, sd[i][j]);
        float e[cS], ssum = 0.f;
        #pragma unroll
        for (int i = 0; i < cS; i++) { e[i] = expf(sd[i][j] - m); ssum += e[i]; }
        const float inv = 1.f / ssum;
        #pragma unroll
        for (int i = 0; i < cS; i++) {
            const float a = e[i] * inv;
            sd[i][j] = a;
            attn_out[(size_t)(b * cS + i) * cN + j] = a;
        }
    }
    __syncthreads();
    for (int d = tid * 2; d < cD; d += 512) {
        float a0[cS], a1[cS];
        #pragma unroll
        for (int i = 0; i < cS; i++) { a0[i] = 0.f; a1[i] = 0.f; }
        for (int j = 0; j < cN; j++) {
            const float2 vj = *(const float2*)(vv + (size_t)(b * cN + j) * cD + d);
            #pragma unroll
            for (int i = 0; i < cS; i++) {
                a0[i] = fmaf(sd[i][j], vj.x, a0[i]);
                a1[i] = fmaf(sd[i][j], vj.y, a1[i]);
            }
        }
        #pragma unroll
        for (int i = 0; i < cS; i++) {
            const int row = b * cS + i;
            put1((char*)upd_h, row >> 7, K1D, row & 127, d, packh(a0[i], a1[i]));
        }
    }
}

__global__ void __launch_bounds__(256) gru_k(
    const float* __restrict__ gi, const float* __restrict__ gh,
    const float* __restrict__ h, float* __restrict__ hnew)
{
    const size_t idx = (size_t)blockIdx.x * 256 + threadIdx.x;
    const int row = (int)(idx / cF), f = (int)(idx % cF);
    const size_t o = (size_t)row * G3 + f;
    const float ir = gi[o], iz = gi[o + cF], inn = gi[o + 2 * cF];
    const float hr = gh[o], hz = gh[o + cF], hn = gh[o + 2 * cF];
    const float hp = h[(size_t)row * cF + f];
    const float r = 1.f / (1.f + expf(-(ir + hr)));
    const float z = 1.f / (1.f + expf(-(iz + hz)));
    const float n = tanhf(inn + r * hn);
    hnew[(size_t)row * cF + f] = (1.f - z) * n + z * hp;
}

__global__ void __launch_bounds__(256) init_h_k(const float* __restrict__ cand, float* __restrict__ h) {
    const size_t idx = (size_t)blockIdx.x * 256 + threadIdx.x;
    const int row = (int)(idx / cF), f = (int)(idx % cF);
    h[idx] = cand[(size_t)row * cD + f];
}
__global__ void __launch_bounds__(256) out_slots_k(
    const float* __restrict__ cand, const float* __restrict__ h, float* __restrict__ out) {
    const size_t idx = (size_t)blockIdx.x * 256 + threadIdx.x;
    const int row = (int)(idx / cD), c = (int)(idx % cD);
    out[idx] = (c < cF) ? h[(size_t)row * cF + c] : cand[idx];
}
__global__ void __launch_bounds__(256) out_attn_k(const float* __restrict__ attn, float* __restrict__ out) {
    const size_t idx = (size_t)blockIdx.x * 256 + threadIdx.x;
    out[(size_t)BSr * cD + idx] = attn[idx];
}

extern "C" void kernel_launch(void* const* d_in, const int* in_sizes, int n_in,
                              void* d_out, int out_size)
{
    const float* cand = (const float*)d_in[0];
    const float* pano = (const float*)d_in[1];
    const void* mask = d_in[2];
    const float* Wq = (const float*)d_in[3];
    const float* bq = (const float*)d_in[4];
    const float* Wk = (const float*)d_in[5];
    const float* bk = (const float*)d_in[6];
    const float* Wv = (const float*)d_in[7];
    const float* bv = (const float*)d_in[8];
    const float* W_ih = (const float*)d_in[9];
    const float* b_ih = (const float*)d_in[10];
    const float* W_hh = (const float*)d_in[11];
    const float* b_hh = (const float*)d_in[12];
    const float* W1 = (const float*)d_in[13];
    const float* b1 = (const float*)d_in[14];
    const float* W2 = (const float*)d_in[15];
    const float* b2 = (const float*)d_in[16];
    const float* ln_in_g = (const float*)d_in[17];
    const float* ln_in_b = (const float*)d_in[18];
    const float* ln_slots_g = (const float*)d_in[19];
    const float* ln_slots_b = (const float*)d_in[20];
    const float* ln_pre_g = (const float*)d_in[21];
    const float* ln_pre_b = (const float*)d_in[22];
    float* out = (float*)d_out;

    float *p_k, *p_v, *p_q, *p_gi, *p_gh, *p_h, *p_hnew, *p_attn;
    __nv_bfloat16 *b_pano, *b_s, *b_wq, *b_wk;
    __half *h_pano, *h_upd, *h_h, *h_pre, *h_hid, *h_wv, *h_wih, *h_whh, *h_w1, *h_w2;
    cudaGetSymbolAddress((void**)&p_k, g_k);
    cudaGetSymbolAddress((void**)&p_v, g_v);
    cudaGetSymbolAddress((void**)&p_q, g_q);
    cudaGetSymbolAddress((void**)&p_gi, g_gi);
    cudaGetSymbolAddress((void**)&p_gh, g_gh);
    cudaGetSymbolAddress((void**)&p_h, g_h);
    cudaGetSymbolAddress((void**)&p_hnew, g_hnew);
    cudaGetSymbolAddress((void**)&p_attn, g_attn);
    cudaGetSymbolAddress((void**)&b_pano, g_pano_b);
    cudaGetSymbolAddress((void**)&b_s, g_s_b);
    cudaGetSymbolAddress((void**)&b_wq, g_wq_b);
    cudaGetSymbolAddress((void**)&b_wk, g_wk_b);
    cudaGetSymbolAddress((void**)&h_pano, g_pano_h);
    cudaGetSymbolAddress((void**)&h_upd, g_upd_h);
    cudaGetSymbolAddress((void**)&h_h, g_h_h);
    cudaGetSymbolAddress((void**)&h_pre, g_pre_h);
    cudaGetSymbolAddress((void**)&h_hid, g_hid_h);
    cudaGetSymbolAddress((void**)&h_wv, g_wv_h);
    cudaGetSymbolAddress((void**)&h_wih, g_wih_h);
    cudaGetSymbolAddress((void**)&h_whh, g_whh_h);
    cudaGetSymbolAddress((void**)&h_w1, g_w1_h);
    cudaGetSymbolAddress((void**)&h_w2, g_w2_h);

    cudaFuncSetAttribute(gemm_mma<false, false, 0, 0>, cudaFuncAttributeMaxDynamicSharedMemorySize, SMB);
    cudaFuncSetAttribute(gemm_mma<true, false, 3, 1>, cudaFuncAttributeMaxDynamicSharedMemorySize, SMB);
    cudaFuncSetAttribute(gemm_mma<false, true, 2, 1>, cudaFuncAttributeMaxDynamicSharedMemorySize, SMB);
    cudaFuncSetAttribute(gemm_dual<0, 1>, cudaFuncAttributeMaxDynamicSharedMemorySize, SMB);
    cudaFuncSetAttribute(gemm_dual<1, 1>, cudaFuncAttributeMaxDynamicSharedMemorySize, SMB);

    detect_mask_k<<<1, 256>>>((const unsigned char*)mask);

    // weight conversions
    conv_w_k<<<(2176 * 1088) / 256, 256>>>(Wq, b_wq, 2176, K1D);
    conv_w_k<<<(2176 * 1088) / 256, 256>>>(Wk, b_wk, 2176, K1D);
    conv_w_h_k<<<(2176 * 1088) / 256, 256>>>(Wv, h_wv, 2176, K1D);
    conv_w_h_k<<<(6144 * 1088) / 256, 256>>>(W_ih, h_wih, 2176, K1D);
    conv_w_h_k<<<(6144 * 1024) / 256, 256>>>(W_hh, h_whh, 2048, K1F);
    conv_w_h_k<<<(2176 * 1024) / 256, 256>>>(W1, h_w1, 2048, K1F);
    conv_w_h_k<<<(2048 * 1088) / 256, 256>>>(W2, h_w2, 2176, K1D);

    // pano LN: bf16 3-panel (k) + fp16 1-panel (v)
    ln_conv_k<true, true, true><<<BNr, 256>>>(pano, cD, pano, ln_in_g, ln_in_b,
                                              b_pano, K1D, h_pano, K1D, 2176);
    {
        GemmP pk = { b_pano, b_wk, bk, p_k, KTD };
        GemmP pv = { h_pano, h_wv, bv, p_v, K1D };
        gemm_dual<0, 1><<<dim3(17, 288, 2), 256, SMB>>>(pk, pv, 2176);
    }

    init_h_k<<<(BSr * cF) / 256, 256>>>(cand, p_h);
    conv_act_h_k<<<(BSr * 1024) / 256, 256>>>(p_h, cF, h_h, 2048, K1F);

    for (int it = 0; it < 3; it++) {
        ln_conv_k<true, true, false><<<BSr, 256>>>(p_h, cF, cand, ln_slots_g, ln_slots_b,
                                                   b_s, K1D, nullptr, 0, 2176);
        gemm_mma<false, false, 0, 0><<<dim3(17, 80), 256, SMB>>>(b_s, b_wq, bq, nullptr, p_q, KTD, 2176, nullptr, 0);
        attn_k<<<cB, 256>>>(mask, p_q, p_k, p_v, p_attn, h_upd);
        {
            GemmP pi = { h_upd, h_wih, b_ih, p_gi, K1D };
            GemmP ph = { h_h,   h_whh, b_hh, p_gh, K1F };
            gemm_dual<1, 1><<<dim3(48, 80, 2), 256, SMB>>>(pi, ph, 6144);
        }
        gru_k<<<(BSr * cF) / 256, 256>>>(p_gi, p_gh, p_h, p_hnew);
        ln_conv_k<false, false, true><<<BSr, 256>>>(p_hnew, cF, nullptr, ln_pre_g, ln_pre_b,
                                                    nullptr, 0, h_pre, K1F, 2048);
        gemm_mma<true, false, 3, 1><<<dim3(17, 80), 256, SMB>>>(h_pre, h_w1, b1, nullptr, nullptr, K1F, 2176, h_hid, K1D);
        gemm_mma<false, true, 2, 1><<<dim3(16, 80), 256, SMB>>>(h_hid, h_w2, b2, p_hnew, p_h, K1D, 2048, h_h, K1F);
    }

    out_slots_k<<<(BSr * cD) / 256, 256>>>(cand, p_h, out);
    out_attn_k<<<(BSr * cN) / 256, 256>>>(p_attn, out);
}

// round 11
// speedup vs baseline: 2.3270x; 1.0586x over previous
#include <cuda_runtime.h>
#include <cuda_bf16.h>
#include <cuda_fp16.h>
#include <math.h>
#include <stdint.h>

constexpr int cB = 1024, cS = 10, cN = 36, cF = 2048, cD = 2176;
constexpr int BSr = cB * cS, BNr = cB * cN, G3 = 3 * cF;
constexpr int K3D = 3 * cD;                      // 6528
constexpr int KTD = K3D / 64;                    // 102 (k/q bf16 3-pass tiles)
constexpr int K1D = cD / 64, K1F = cF / 64;      // 34 / 32 (base k-tiles)

// fp32 scratch
__device__ float g_k[(size_t)BNr * cD];
__device__ float g_v[(size_t)BNr * cD];
__device__ float g_q[(size_t)BSr * cD];
__device__ float g_gi[(size_t)BSr * G3];
__device__ float g_gh[(size_t)BSr * G3];
__device__ float g_h[(size_t)BSr * cF];
__device__ float g_hnew[(size_t)BSr * cF];
__device__ float g_attn[(size_t)BSr * cN];
__device__ int g_mask_mode;

// bf16 split operands ([hi|hi|lo] for A, [hi|lo|hi] for W) — k and q GEMMs
__device__ __align__(256) __nv_bfloat16 g_pano_b[(size_t)BNr * K3D];
__device__ __align__(256) __nv_bfloat16 g_s_b [(size_t)BSr * K3D];
__device__ __align__(256) __nv_bfloat16 g_wq_b [(size_t)2176 * K3D];
__device__ __align__(256) __nv_bfloat16 g_wk_b [(size_t)2176 * K3D];

// fp16 single-panel operands (1-pass GEMMs: v, gi, gh, W1, W2)
__device__ __align__(256) __half g_pano_h[(size_t)BNr * cD];
__device__ __align__(256) __half g_upd_h[(size_t)BSr * cD];
__device__ __align__(256) __half g_h_h [(size_t)BSr * cF];
__device__ __align__(256) __half g_pre_h[(size_t)BSr * cF];
__device__ __align__(256) __half g_hid_h[(size_t)BSr * cD];
__device__ __align__(256) __half g_wv_h [(size_t)2176 * cD];
__device__ __align__(256) __half g_wih_h[(size_t)6144 * cD];
__device__ __align__(256) __half g_whh_h[(size_t)6144 * cF];
__device__ __align__(256) __half g_w1_h [(size_t)2176 * cF];
__device__ __align__(256) __half g_w2_h [(size_t)2048 * cD];

__device__ __forceinline__ uint32_t smem_u32(const void* p) {
    uint32_t a;
    asm("{ .reg .u64 t; cvta.to.shared.u64 t, %1; cvt.u32.u64 %0, t; }" : "=r"(a) : "l"(p));
    return a;
}
#define MBAR_INIT(a, c) asm volatile("mbarrier.init.shared.b64 [%0], %1;" :: "r"(a), "r"(c) : "memory")
#define MBAR_EXPECT_TX(a, b) asm volatile("mbarrier.arrive.expect_tx.shared.b64 _, [%0], %1;" :: "r"(a), "r"(b) : "memory")
#define MBAR_ARRIVE(a) asm volatile("mbarrier.arrive.shared.b64 _, [%0];" :: "r"(a) : "memory")
#define MBAR_WAIT(a, p) do { \
    uint32_t _m = (a), _p = (p), _d; \
    asm volatile("{\n\t.reg .pred q;\n\tmbarrier.try_wait.parity.acquire.cta.shared::cta.b64 q, [%1], %2;\n\tselp.b32 %0, 1, 0, q;\n\t}" \
        : "=r"(_d) : "r"(_m), "r"(_p) : "memory"); \
    if (!_d) { \
        asm volatile("{\n\t.reg .pred P1;\n\tWL_%=:\n\tmbarrier.try_wait.parity.acquire.cta.shared::cta.b64 P1, [%0], %1, 0x989680;\n\t@P1 bra.uni WD_%=;\n\tbra.uni WL_%=;\n\tWD_%=:\n\t}" \
            :: "r"(_m), "r"(_p) : "memory"); \
    } } while (0)

__device__ __forceinline__ void bulk_g2s(uint32_t dst, const void* src, uint32_t bytes, uint32_t mbar) {
    asm volatile("cp.async.bulk.shared::cluster.global.mbarrier::complete_tx::bytes [%0], [%1], %2, [%3];"
        :: "r"(dst), "l"(src), "r"(bytes), "r"(mbar) : "memory");
}

__device__ __forceinline__ uint32_t packbf(float a, float b) {
    return (uint32_t)__bfloat16_as_ushort(__float2bfloat16_rn(a)) |
           ((uint32_t)__bfloat16_as_ushort(__float2bfloat16_rn(b)) << 16);
}
__device__ __forceinline__ uint32_t packh(float a, float b) {
    __half2 h = __floats2half2_rn(a, b);
    return *reinterpret_cast<uint32_t*>(&h);
}
__device__ __forceinline__ float residf(float a) {
    return a - __bfloat162float(__float2bfloat16_rn(a));
}
__device__ __forceinline__ uint32_t swz(uint32_t o) { return o ^ ((o >> 3) & 0x70); }

// single-panel write (fp16 path)
__device__ __forceinline__ void put1(char* base, int rb, int kt1, int r, int col, uint32_t v) {
    const int t = col >> 6, cc = col & 63;
    *(uint32_t*)(base + (((size_t)rb * kt1 + t) << 14) + swz(((uint32_t)r << 7) + ((uint32_t)cc << 1))) = v;
}
// A-side bf16 split: hi at t, hi at t+kt1, lo at t+2*kt1
__device__ __forceinline__ void put3a(char* base, int rb, int kt1, int r, int col,
                                      uint32_t hi, uint32_t lo) {
    const int t = col >> 6, cc = col & 63;
    const uint32_t so = swz(((uint32_t)r << 7) + ((uint32_t)cc << 1));
    char* p = base + (((size_t)rb * 3 * kt1 + t) << 14) + so;
    *(uint32_t*)p = hi;
    *(uint32_t*)(p + ((size_t)kt1 << 14)) = hi;
    *(uint32_t*)(p + ((size_t)(2 * kt1) << 14)) = lo;
}
// W-side bf16 split: hi at t, lo at t+kt1, hi at t+2*kt1
__device__ __forceinline__ void put3w(char* base, int rb, int kt1, int r, int col,
                                      uint32_t hi, uint32_t lo) {
    const int t = col >> 6, cc = col & 63;
    const uint32_t so = swz(((uint32_t)r << 7) + ((uint32_t)cc << 1));
    char* p = base + (((size_t)rb * 3 * kt1 + t) << 14) + so;
    *(uint32_t*)p = hi;
    *(uint32_t*)(p + ((size_t)kt1 << 14)) = lo;
    *(uint32_t*)(p + ((size_t)(2 * kt1) << 14)) = hi;
}

__global__ void detect_mask_k(const unsigned char* __restrict__ m) {
    __shared__ int c1, c3f;
    if (threadIdx.x == 0) { c1 = 0; c3f = 0; }
    __syncthreads();
    int l1 = 0, l3 = 0;
    for (int i = threadIdx.x; i < BSr; i += 256) {
        unsigned char v = m[i];
        if ((i & 3) != 0 && v == 1) l1++;
        if (v == 0x3f) l3++;
    }
    atomicAdd(&c1, l1); atomicAdd(&c3f, l3);
    __syncthreads();
    if (threadIdx.x == 0) g_mask_mode = (c3f > 0) ? 2 : (c1 > 0 ? 0 : 1);
}

// LN over cF cols of x (stride xs); cols [cF,Kx) from tailsrc (stride cD).
template <bool TAIL, bool WBF, bool WH>
__global__ void __launch_bounds__(256) ln_conv_k(
    const float* __restrict__ x, int xs, const float* __restrict__ tailsrc,
    const float* __restrict__ gam, const float* __restrict__ bet,
    __nv_bfloat16* __restrict__ dstB, int kt1,
    __half* __restrict__ dstH, int kth, int Kx)
{
    const int row = blockIdx.x, tid = threadIdx.x;
    const float* xr = x + (size_t)row * xs;
    float s = 0.f, s2 = 0.f;
    for (int c = tid * 4; c < cF; c += 1024) {
        float4 v = *reinterpret_cast<const float4*>(xr + c);
        s += v.x + v.y + v.z + v.w;
        s2 += v.x * v.x + v.y * v.y + v.z * v.z + v.w * v.w;
    }
    #pragma unroll
    for (int o = 16; o; o >>= 1) {
        s += __shfl_xor_sync(0xffffffffu, s, o);
        s2 += __shfl_xor_sync(0xffffffffu, s2, o);
    }
    __shared__ float ws[8], ws2[8];
    const int warp = tid >> 5, lane = tid & 31;
    if (lane == 0) { ws[warp] = s; ws2[warp] = s2; }
    __syncthreads();
    if (tid == 0) {
        float a = 0.f, b2 = 0.f;
        #pragma unroll
        for (int w = 0; w < 8; w++) { a += ws[w]; b2 += ws2[w]; }
        ws[0] = a; ws2[0] = b2;
    }
    __syncthreads();
    const float mean = ws[0] * (1.f / cF);
    const float rstd = rsqrtf(ws2[0] * (1.f / cF) - mean * mean + 1e-5f);
    const int mt = row >> 7, r = row & 127;
    for (int p = tid; p < (Kx >> 1); p += 256) {
        const int c = 2 * p;
        float a, b;
        if (c < cF) {
            a = (xr[c] - mean) * rstd * gam[c] + bet[c];
            b = (xr[c + 1] - mean) * rstd * gam[c + 1] + bet[c + 1];
        } else {
            a = TAIL ? tailsrc[(size_t)row * cD + c] : 0.f;
            b = TAIL ? tailsrc[(size_t)row * cD + c + 1] : 0.f;
        }
        if (WBF) put3a((char*)dstB, mt, kt1, r, c, packbf(a, b), packbf(residf(a), residf(b)));
        if (WH)  put1((char*)dstH, mt, kth, r, c, packh(a, b));
    }
}

__global__ void __launch_bounds__(256) conv_act_h_k(
    const float* __restrict__ x, int xs, __half* __restrict__ dst, int Kx, int kt1)
{
    const int Kh = Kx >> 1;
    const size_t idx = (size_t)blockIdx.x * 256 + threadIdx.x;
    const int row = (int)(idx / Kh), c = 2 * (int)(idx % Kh);
    put1((char*)dst, row >> 7, kt1, row & 127, c,
         packh(x[(size_t)row * xs + c], x[(size_t)row * xs + c + 1]));
}

__global__ void __launch_bounds__(256) conv_w_h_k(
    const float* __restrict__ w, __half* __restrict__ dst, int Kx, int kt1)
{
    const int Kh = Kx >> 1;
    const size_t idx = (size_t)blockIdx.x * 256 + threadIdx.x;
    const int row = (int)(idx / Kh), c = 2 * (int)(idx % Kh);
    put1((char*)dst, row >> 7, kt1, row & 127, c,
         packh(w[(size_t)row * Kx + c], w[(size_t)row * Kx + c + 1]));
}

__global__ void __launch_bounds__(256) conv_w_k(
    const float* __restrict__ w, __nv_bfloat16* __restrict__ dst, int Kx, int kt1)
{
    const int Kh = Kx >> 1;
    const size_t idx = (size_t)blockIdx.x * 256 + threadIdx.x;
    const int row = (int)(idx / Kh), c = 2 * (int)(idx % Kh);
    const float a = w[(size_t)row * Kx + c], b = w[(size_t)row * Kx + c + 1];
    put3w((char*)dst, row >> 7, kt1, row & 127, c, packbf(a, b), packbf(residf(a), residf(b)));
}

// DT: 0 = bf16 mma, 1 = fp16 mma
template <int DT>
__device__ __forceinline__ void mma16816(float* c, const uint32_t* a, uint32_t b0, uint32_t b1) {
    if (DT == 0)
        asm volatile("mma.sync.aligned.m16n8k16.row.col.f32.bf16.bf16.f32 "
            "{%0,%1,%2,%3}, {%4,%5,%6,%7}, {%8,%9}, {%0,%1,%2,%3};"
            : "+f"(c[0]), "+f"(c[1]), "+f"(c[2]), "+f"(c[3])
            : "r"(a[0]), "r"(a[1]), "r"(a[2]), "r"(a[3]), "r"(b0), "r"(b1));
    else
        asm volatile("mma.sync.aligned.m16n8k16.row.col.f32.f16.f16.f32 "
            "{%0,%1,%2,%3}, {%4,%5,%6,%7}, {%8,%9}, {%0,%1,%2,%3};"
            : "+f"(c[0]), "+f"(c[1]), "+f"(c[2]), "+f"(c[3])
            : "r"(a[0]), "r"(a[1]), "r"(a[2]), "r"(a[3]), "r"(b0), "r"(b1));
}

// mma.sync GEMM core: BM=BN=128 BK=64, 8 warps, 3-stage bulk pipeline.
// SPLIT: 0 = fp32 C only; 2 = fp32 C + fp16 panel; 3 = fp16 panel only.
constexpr int STG = 32768, SD0 = 1024, SMB = SD0 + 3 * STG;

template <bool RELU, bool ADD, int SPLIT, int DT>
__device__ __forceinline__ void gemm_core(
    const void* __restrict__ Ab, const void* __restrict__ Wb,
    const float* __restrict__ bias, const float* __restrict__ addsrc,
    float* __restrict__ C, int ktiles, int Nc,
    void* __restrict__ sdst, int skt1, int nt, int mt)
{
    extern __shared__ __align__(1024) char smem[];
    const uint32_t sb = smem_u32(smem);
    const int tid = threadIdx.x, warp = tid >> 5, lane = tid & 31;

    if (tid == 0) {
        #pragma unroll
        for (int s = 0; s < 3; s++) { MBAR_INIT(sb + 8 * s, 1); MBAR_INIT(sb + 24 + 8 * s, 256); }
    }
    __syncthreads();

    const char* Ag = (const char*)Ab + (size_t)mt * ktiles * 16384;
    const char* Wg = (const char*)Wb + (size_t)nt * ktiles * 16384;

    if (tid == 0) {
        #pragma unroll
        for (int s = 0; s < 3; s++) {
            MBAR_EXPECT_TX(sb + 8 * s, 32768);
            bulk_g2s(sb + SD0 + s * STG, Ag + (size_t)s * 16384, 16384, sb + 8 * s);
            bulk_g2s(sb + SD0 + s * STG + 16384, Wg + (size_t)s * 16384, 16384, sb + 8 * s);
        }
    }

    const int m0w = (warp >> 1) << 5;
    const int n0w = (warp & 1) << 6;
    const int arow = m0w + (lane & 15);
    const uint32_t aoff0 = (uint32_t)arow << 7;
    const uint32_t axor = (uint32_t)(arow & 7) << 4;
    const uint32_t akh = (uint32_t)(lane >> 4) << 4;
    const uint32_t boff0 = (uint32_t)(n0w + lane) << 7;
    const uint32_t bxor = (uint32_t)(lane & 7) << 4;

    float acc[2][8][4];
    #pragma unroll
    for (int i = 0; i < 2; i++)
        #pragma unroll
        for (int j = 0; j < 8; j++)
            #pragma unroll
            for (int q = 0; q < 4; q++) acc[i][j][q] = 0.f;

    int s = 0, ph = 0;
    #pragma unroll 1
    for (int kt = 0; kt < ktiles; kt++) {
        MBAR_WAIT(sb + 8 * s, ph);
        const uint32_t As = sb + SD0 + s * STG;
        const uint32_t Bs = As + 16384;
        #pragma unroll
        for (int kk = 0; kk < 4; kk++) {
            uint32_t a[2][4];
            const uint32_t kbA = ((kk << 5) | akh) ^ axor;
            #pragma unroll
            for (int im = 0; im < 2; im++) {
                uint32_t ad = As + aoff0 + (im << 11) + kbA;
                asm volatile("ldmatrix.sync.aligned.m8n8.x4.shared.b16 {%0,%1,%2,%3}, [%4];"
                    : "=r"(a[im][0]), "=r"(a[im][1]), "=r"(a[im][2]), "=r"(a[im][3]) : "r"(ad));
            }
            uint32_t b0[8], b1[8];
            #pragma unroll
            for (int q = 0; q < 2; q++) {
                uint32_t bd = Bs + boff0 + (q << 12);
                uint32_t k0 = (kk << 5) ^ bxor;
                uint32_t k1 = ((kk << 5) | 16) ^ bxor;
                asm volatile("ldmatrix.sync.aligned.m8n8.x4.shared.b16 {%0,%1,%2,%3}, [%4];"
                    : "=r"(b0[q*4+0]), "=r"(b0[q*4+1]), "=r"(b0[q*4+2]), "=r"(b0[q*4+3]) : "r"(bd + k0));
                asm volatile("ldmatrix.sync.aligned.m8n8.x4.shared.b16 {%0,%1,%2,%3}, [%4];"
                    : "=r"(b1[q*4+0]), "=r"(b1[q*4+1]), "=r"(b1[q*4+2]), "=r"(b1[q*4+3]) : "r"(bd + k1));
            }
            #pragma unroll
            for (int im = 0; im < 2; im++)
                #pragma unroll
                for (int ng = 0; ng < 8; ng++)
                    mma16816<DT>(acc[im][ng], a[im], b0[ng], b1[ng]);
        }
        MBAR_ARRIVE(sb + 24 + 8 * s);
        if (tid == 0 && kt + 3 < ktiles) {
            MBAR_WAIT(sb + 24 + 8 * s, ph);
            MBAR_EXPECT_TX(sb + 8 * s, 32768);
            bulk_g2s(sb + SD0 + s * STG, Ag + (size_t)(kt + 3) * 16384, 16384, sb + 8 * s);
            bulk_g2s(sb + SD0 + s * STG + 16384, Wg + (size_t)(kt + 3) * 16384, 16384, sb + 8 * s);
        }
        if (++s == 3) { s = 0; ph ^= 1; }
    }

    const int rb = mt * 128 + m0w + (lane >> 2);
    const int cb = nt * 128 + n0w + ((lane & 3) << 1);
    #pragma unroll
    for (int im = 0; im < 2; im++) {
        #pragma unroll
        for (int ng = 0; ng < 8; ng++) {
            const int r0 = rb + im * 16, c = cb + ng * 8;
            const float bx = bias[c], by = bias[c + 1];
            float2 v0 = make_float2(acc[im][ng][0] + bx, acc[im][ng][1] + by);
            float2 v1 = make_float2(acc[im][ng][2] + bx, acc[im][ng][3] + by);
            if (RELU) {
                v0.x = fmaxf(v0.x, 0.f); v0.y = fmaxf(v0.y, 0.f);
                v1.x = fmaxf(v1.x, 0.f); v1.y = fmaxf(v1.y, 0.f);
            }
            if (ADD) {
                const float2 a0 = *(const float2*)(addsrc + (size_t)r0 * Nc + c);
                const float2 a1 = *(const float2*)(addsrc + (size_t)(r0 + 8) * Nc + c);
                v0.x += a0.x; v0.y += a0.y; v1.x += a1.x; v1.y += a1.y;
            }
            if (SPLIT != 3) {
                *(float2*)(C + (size_t)r0 * Nc + c) = v0;
                *(float2*)(C + (size_t)(r0 + 8) * Nc + c) = v1;
            }
            if (SPLIT == 2 || SPLIT == 3) {
                put1((char*)sdst, r0 >> 7, skt1, r0 & 127, c, packh(v0.x, v0.y));
                put1((char*)sdst, (r0 + 8) >> 7, skt1, (r0 + 8) & 127, c, packh(v1.x, v1.y));
            }
        }
    }
}

template <bool RELU, bool ADD, int SPLIT, int DT>
__global__ void __launch_bounds__(256, 2) gemm_mma(
    const void* __restrict__ Ab, const void* __restrict__ Wb,
    const float* __restrict__ bias, const float* __restrict__ addsrc,
    float* __restrict__ C, int ktiles, int Nc,
    void* __restrict__ sdst, int skt1)
{
    gemm_core<RELU, ADD, SPLIT, DT>(Ab, Wb, bias, addsrc, C, ktiles, Nc, sdst, skt1,
                                    blockIdx.x, blockIdx.y);
}

struct GemmP {
    const void* A;
    const void* W;
    const float* bias;
    float* C;
    int ktiles;
};

template <int DT0, int DT1>
__global__ void __launch_bounds__(256, 2) gemm_dual(GemmP p0, GemmP p1, int Nc) {
    if (blockIdx.z == 0)
        gemm_core<false, false, 0, DT0>(p0.A, p0.W, p0.bias, nullptr, p0.C, p0.ktiles, Nc,
                                        nullptr, 0, blockIdx.x, blockIdx.y);
    else
        gemm_core<false, false, 0, DT1>(p1.A, p1.W, p1.bias, nullptr, p1.C, p1.ktiles, Nc,
                                        nullptr, 0, blockIdx.x, blockIdx.y);
}

// attention v2: q staged in smem (read once), k streamed once per j.
constexpr int ASMB = cS * cD * 4 + cS * cN * 4 + cS * 4 + 256;  // ~88.8 KB

__global__ void __launch_bounds__(256, 2) attn_k(
    const void* __restrict__ mask, const float* __restrict__ q,
    const float* __restrict__ kk, const float* __restrict__ vv,
    float* __restrict__ attn_out, __half* __restrict__ upd_h)
{
    extern __shared__ __align__(16) float sq[];           // cS*cD
    float* sd = sq + cS * cD;                             // cS*cN
    float* smask = sd + cS * cN;                          // cS
    const int b = blockIdx.x, tid = threadIdx.x;
    if (tid < cS) {
        const int mm = g_mask_mode;
        const int idx = b * cS + tid;
        bool mk;
        if (mm == 0)      mk = ((const unsigned char*)mask)[idx] != 0;
        else if (mm == 1) mk = ((const int*)mask)[idx] != 0;
        else              mk = ((const float*)mask)[idx] != 0.f;
        smask[tid] = mk ? 1.f : 0.f;
    }
    // stage q block into smem
    for (int p = tid * 4; p < cS * cD; p += 1024)
        *reinterpret_cast<float4*>(sq + p) =
            *reinterpret_cast<const float4*>(q + (size_t)b * cS * cD + p);
    __syncthreads();

    const int warp = tid >> 5, lane = tid & 31;
    const float scale = rsqrtf((float)cD);
    for (int j = warp; j < cN; j += 8) {
        const float* kr = kk + (size_t)(b * cN + j) * cD;
        float acc[cS];
        #pragma unroll
        for (int i = 0; i < cS; i++) acc[i] = 0.f;
        for (int d = lane * 4; d < cD; d += 128) {
            const float4 kv = *reinterpret_cast<const float4*>(kr + d);
            #pragma unroll
            for (int i = 0; i < cS; i++) {
                const float4 qv = *reinterpret_cast<const float4*>(sq + i * cD + d);
                acc[i] += kv.x * qv.x + kv.y * qv.y + kv.z * qv.z + kv.w * qv.w;
            }
        }
        #pragma unroll
        for (int i = 0; i < cS; i++) {
            float r = acc[i];
            #pragma unroll
            for (int o = 16; o; o >>= 1) r += __shfl_xor_sync(0xffffffffu, r, o);
            if (lane == 0) sd[i * cN + j] = (smask[i] > 0.f) ? -INFINITY : r * scale;
        }
    }
    __syncthreads();
    if (tid < cN) {
        const int j = tid;
        float m = -INFINITY;
        #pragma unroll
        for (int i = 0; i < cS; i++) m = fmaxf(m, sd[i * cN + j]);
        float e[cS], ssum = 0.f;
        #pragma unroll
        for (int i = 0; i < cS; i++) { e[i] = expf(sd[i * cN + j] - m); ssum += e[i]; }
        const float inv = 1.f / ssum;
        #pragma unroll
        for (int i = 0; i < cS; i++) {
            const float a = e[i] * inv;
            sd[i * cN + j] = a;
            attn_out[(size_t)(b * cS + i) * cN + j] = a;
        }
    }
    __syncthreads();
    for (int d = tid * 2; d < cD; d += 512) {
        float a0[cS], a1[cS];
        #pragma unroll
        for (int i = 0; i < cS; i++) { a0[i] = 0.f; a1[i] = 0.f; }
        for (int j = 0; j < cN; j++) {
            const float2 vj = *(const float2*)(vv + (size_t)(b * cN + j) * cD + d);
            #pragma unroll
            for (int i = 0; i < cS; i++) {
                a0[i] = fmaf(sd[i * cN + j], vj.x, a0[i]);
                a1[i] = fmaf(sd[i * cN + j], vj.y, a1[i]);
            }
        }
        #pragma unroll
        for (int i = 0; i < cS; i++) {
            const int row = b * cS + i;
            put1((char*)upd_h, row >> 7, K1D, row & 127, d, packh(a0[i], a1[i]));
        }
    }
}

// fused GRU + pre-LN + fp16 panel conversion (one block per row)
__global__ void __launch_bounds__(256) gru_ln_k(
    const float* __restrict__ gi, const float* __restrict__ gh,
    const float* __restrict__ h,
    const float* __restrict__ gam, const float* __restrict__ bet,
    float* __restrict__ hnew, __half* __restrict__ preH)
{
    const int row = blockIdx.x, tid = threadIdx.x;
    const size_t o = (size_t)row * G3;
    const size_t oh = (size_t)row * cF;
    float nv[8];
    float s = 0.f, s2 = 0.f;
    #pragma unroll
    for (int g = 0; g < 2; g++) {
        const int f = tid * 8 + g * 4;
        const float4 ir4 = *(const float4*)(gi + o + f);
        const float4 iz4 = *(const float4*)(gi + o + cF + f);
        const float4 in4 = *(const float4*)(gi + o + 2 * cF + f);
        const float4 hr4 = *(const float4*)(gh + o + f);
        const float4 hz4 = *(const float4*)(gh + o + cF + f);
        const float4 hn4 = *(const float4*)(gh + o + 2 * cF + f);
        const float4 hp4 = *(const float4*)(h + oh + f);
        const float ir[4] = {ir4.x, ir4.y, ir4.z, ir4.w};
        const float iz[4] = {iz4.x, iz4.y, iz4.z, iz4.w};
        const float in_[4] = {in4.x, in4.y, in4.z, in4.w};
        const float hr[4] = {hr4.x, hr4.y, hr4.z, hr4.w};
        const float hz[4] = {hz4.x, hz4.y, hz4.z, hz4.w};
        const float hn[4] = {hn4.x, hn4.y, hn4.z, hn4.w};
        const float hp[4] = {hp4.x, hp4.y, hp4.z, hp4.w};
        float out4[4];
        #pragma unroll
        for (int e = 0; e < 4; e++) {
            const float r = 1.f / (1.f + expf(-(ir[e] + hr[e])));
            const float z = 1.f / (1.f + expf(-(iz[e] + hz[e])));
            const float n = tanhf(in_[e] + r * hn[e]);
            const float hv = (1.f - z) * n + z * hp[e];
            out4[e] = hv;
            nv[g * 4 + e] = hv;
            s += hv; s2 += hv * hv;
        }
        *(float4*)(hnew + oh + f) = make_float4(out4[0], out4[1], out4[2], out4[3]);
    }
    #pragma unroll
    for (int o2 = 16; o2; o2 >>= 1) {
        s += __shfl_xor_sync(0xffffffffu, s, o2);
        s2 += __shfl_xor_sync(0xffffffffu, s2, o2);
    }
    __shared__ float ws[8], ws2[8];
    const int warp = tid >> 5, lane = tid & 31;
    if (lane == 0) { ws[warp] = s; ws2[warp] = s2; }
    __syncthreads();
    if (tid == 0) {
        float a = 0.f, b2 = 0.f;
        #pragma unroll
        for (int w = 0; w < 8; w++) { a += ws[w]; b2 += ws2[w]; }
        ws[0] = a; ws2[0] = b2;
    }
    __syncthreads();
    const float mean = ws[0] * (1.f / cF);
    const float rstd = rsqrtf(ws2[0] * (1.f / cF) - mean * mean + 1e-5f);
    const int mt = row >> 7, r = row & 127;
    #pragma unroll
    for (int g = 0; g < 4; g++) {
        const int c = tid * 8 + g * 2;
        const float a = (nv[g * 2] - mean) * rstd * gam[c] + bet[c];
        const float b = (nv[g * 2 + 1] - mean) * rstd * gam[c + 1] + bet[c + 1];
        put1((char*)preH, mt, K1F, r, c, packh(a, b));
    }
}

__global__ void __launch_bounds__(256) init_h_k(const float* __restrict__ cand, float* __restrict__ h) {
    const size_t idx = (size_t)blockIdx.x * 256 + threadIdx.x;
    const int row = (int)(idx / cF), f = (int)(idx % cF);
    h[idx] = cand[(size_t)row * cD + f];
}
__global__ void __launch_bounds__(256) out_slots_k(
    const float* __restrict__ cand, const float* __restrict__ h, float* __restrict__ out) {
    const size_t idx = (size_t)blockIdx.x * 256 + threadIdx.x;
    const int row = (int)(idx / cD), c = (int)(idx % cD);
    out[idx] = (c < cF) ? h[(size_t)row * cF + c] : cand[idx];
}
__global__ void __launch_bounds__(256) out_attn_k(const float* __restrict__ attn, float* __restrict__ out) {
    const size_t idx = (size_t)blockIdx.x * 256 + threadIdx.x;
    out[(size_t)BSr * cD + idx] = attn[idx];
}

extern "C" void kernel_launch(void* const* d_in, const int* in_sizes, int n_in,
                              void* d_out, int out_size)
{
    const float* cand = (const float*)d_in[0];
    const float* pano = (const float*)d_in[1];
    const void* mask = d_in[2];
    const float* Wq = (const float*)d_in[3];
    const float* bq = (const float*)d_in[4];
    const float* Wk = (const float*)d_in[5];
    const float* bk = (const float*)d_in[6];
    const float* Wv = (const float*)d_in[7];
    const float* bv = (const float*)d_in[8];
    const float* W_ih = (const float*)d_in[9];
    const float* b_ih = (const float*)d_in[10];
    const float* W_hh = (const float*)d_in[11];
    const float* b_hh = (const float*)d_in[12];
    const float* W1 = (const float*)d_in[13];
    const float* b1 = (const float*)d_in[14];
    const float* W2 = (const float*)d_in[15];
    const float* b2 = (const float*)d_in[16];
    const float* ln_in_g = (const float*)d_in[17];
    const float* ln_in_b = (const float*)d_in[18];
    const float* ln_slots_g = (const float*)d_in[19];
    const float* ln_slots_b = (const float*)d_in[20];
    const float* ln_pre_g = (const float*)d_in[21];
    const float* ln_pre_b = (const float*)d_in[22];
    float* out = (float*)d_out;

    float *p_k, *p_v, *p_q, *p_gi, *p_gh, *p_h, *p_hnew, *p_attn;
    __nv_bfloat16 *b_pano, *b_s, *b_wq, *b_wk;
    __half *h_pano, *h_upd, *h_h, *h_pre, *h_hid, *h_wv, *h_wih, *h_whh, *h_w1, *h_w2;
    cudaGetSymbolAddress((void**)&p_k, g_k);
    cudaGetSymbolAddress((void**)&p_v, g_v);
    cudaGetSymbolAddress((void**)&p_q, g_q);
    cudaGetSymbolAddress((void**)&p_gi, g_gi);
    cudaGetSymbolAddress((void**)&p_gh, g_gh);
    cudaGetSymbolAddress((void**)&p_h, g_h);
    cudaGetSymbolAddress((void**)&p_hnew, g_hnew);
    cudaGetSymbolAddress((void**)&p_attn, g_attn);
    cudaGetSymbolAddress((void**)&b_pano, g_pano_b);
    cudaGetSymbolAddress((void**)&b_s, g_s_b);
    cudaGetSymbolAddress((void**)&b_wq, g_wq_b);
    cudaGetSymbolAddress((void**)&b_wk, g_wk_b);
    cudaGetSymbolAddress((void**)&h_pano, g_pano_h);
    cudaGetSymbolAddress((void**)&h_upd, g_upd_h);
    cudaGetSymbolAddress((void**)&h_h, g_h_h);
    cudaGetSymbolAddress((void**)&h_pre, g_pre_h);
    cudaGetSymbolAddress((void**)&h_hid, g_hid_h);
    cudaGetSymbolAddress((void**)&h_wv, g_wv_h);
    cudaGetSymbolAddress((void**)&h_wih, g_wih_h);
    cudaGetSymbolAddress((void**)&h_whh, g_whh_h);
    cudaGetSymbolAddress((void**)&h_w1, g_w1_h);
    cudaGetSymbolAddress((void**)&h_w2, g_w2_h);

    cudaFuncSetAttribute(gemm_mma<false, false, 0, 0>, cudaFuncAttributeMaxDynamicSharedMemorySize, SMB);
    cudaFuncSetAttribute(gemm_mma<true, false, 3, 1>, cudaFuncAttributeMaxDynamicSharedMemorySize, SMB);
    cudaFuncSetAttribute(gemm_mma<false, true, 2, 1>, cudaFuncAttributeMaxDynamicSharedMemorySize, SMB);
    cudaFuncSetAttribute(gemm_dual<0, 1>, cudaFuncAttributeMaxDynamicSharedMemorySize, SMB);
    cudaFuncSetAttribute(gemm_dual<1, 1>, cudaFuncAttributeMaxDynamicSharedMemorySize, SMB);
    cudaFuncSetAttribute(attn_k, cudaFuncAttributeMaxDynamicSharedMemorySize, ASMB);

    detect_mask_k<<<1, 256>>>((const unsigned char*)mask);

    // weight conversions
    conv_w_k<<<(2176 * 1088) / 256, 256>>>(Wq, b_wq, 2176, K1D);
    conv_w_k<<<(2176 * 1088) / 256, 256>>>(Wk, b_wk, 2176, K1D);
    conv_w_h_k<<<(2176 * 1088) / 256, 256>>>(Wv, h_wv, 2176, K1D);
    conv_w_h_k<<<(6144 * 1088) / 256, 256>>>(W_ih, h_wih, 2176, K1D);
    conv_w_h_k<<<(6144 * 1024) / 256, 256>>>(W_hh, h_whh, 2048, K1F);
    conv_w_h_k<<<(2176 * 1024) / 256, 256>>>(W1, h_w1, 2048, K1F);
    conv_w_h_k<<<(2048 * 1088) / 256, 256>>>(W2, h_w2, 2176, K1D);

    // pano LN: bf16 3-panel (k) + fp16 1-panel (v)
    ln_conv_k<true, true, true><<<BNr, 256>>>(pano, cD, pano, ln_in_g, ln_in_b,
                                              b_pano, K1D, h_pano, K1D, 2176);
    {
        GemmP pk = { b_pano, b_wk, bk, p_k, KTD };
        GemmP pv = { h_pano, h_wv, bv, p_v, K1D };
        gemm_dual<0, 1><<<dim3(17, 288, 2), 256, SMB>>>(pk, pv, 2176);
    }

    init_h_k<<<(BSr * cF) / 256, 256>>>(cand, p_h);
    conv_act_h_k<<<(BSr * 1024) / 256, 256>>>(p_h, cF, h_h, 2048, K1F);

    for (int it = 0; it < 3; it++) {
        ln_conv_k<true, true, false><<<BSr, 256>>>(p_h, cF, cand, ln_slots_g, ln_slots_b,
                                                   b_s, K1D, nullptr, 0, 2176);
        gemm_mma<false, false, 0, 0><<<dim3(17, 80), 256, SMB>>>(b_s, b_wq, bq, nullptr, p_q, KTD, 2176, nullptr, 0);
        attn_k<<<cB, 256, ASMB>>>(mask, p_q, p_k, p_v, p_attn, h_upd);
        {
            GemmP pi = { h_upd, h_wih, b_ih, p_gi, K1D };
            GemmP ph = { h_h,   h_whh, b_hh, p_gh, K1F };
            gemm_dual<1, 1><<<dim3(48, 80, 2), 256, SMB>>>(pi, ph, 6144);
        }
        gru_ln_k<<<BSr, 256>>>(p_gi, p_gh, p_h, ln_pre_g, ln_pre_b, p_hnew, h_pre);
        gemm_mma<true, false, 3, 1><<<dim3(17, 80), 256, SMB>>>(h_pre, h_w1, b1, nullptr, nullptr, K1F, 2176, h_hid, K1D);
        gemm_mma<false, true, 2, 1><<<dim3(16, 80), 256, SMB>>>(h_hid, h_w2, b2, p_hnew, p_h, K1D, 2048, h_h, K1F);
    }

    out_slots_k<<<(BSr * cD) / 256, 256>>>(cand, p_h, out);
    out_attn_k<<<(BSr * cN) / 256, 256>>>(p_attn, out);
}